// round 2
// baseline (speedup 1.0000x reference)
#include <cuda_runtime.h>
#include <math.h>

// Problem dims (fixed by the reference)
#define TT 4096   // tokens = B*S
#define DD 1024   // model dim
#define FF 4096   // ffn dim
#define EE 8      // experts
#define CC 512    // capacity

// ---------------- scratch (device globals; no allocation allowed) ----------------
__device__ float g_gate[TT];                    // top-1 prob (zeroed if dropped)
__device__ int   g_expert[TT];                  // top-1 expert id
__device__ int   g_tok_of_slot[EE * CC];        // inverse dispatch map, -1 = empty
__device__ float g_expert_in[EE * CC * DD];     // [E,C,D] gate-scaled dispatched tokens (16 MB)
__device__ float g_h[EE * CC * FF];             // [E,C,F] post-GELU hidden (64 MB)

// ---------------- small helpers ----------------
__device__ __forceinline__ unsigned long long dup2(float v) {
    unsigned long long r;
    asm("mov.b64 %0, {%1, %2};" : "=l"(r) : "f"(v), "f"(v));
    return r;
}
__device__ __forceinline__ void ffma2(unsigned long long& c,
                                      unsigned long long a,
                                      unsigned long long b) {
    // packed 2-lane fp32 FMA (PTX ISA 8.6, sm_100+). ptxas never emits this from C++.
    asm("fma.rn.f32x2 %0, %1, %2, %0;" : "+l"(c) : "l"(a), "l"(b));
}
__device__ __forceinline__ float2 unpk2(unsigned long long v) {
    float2 r;
    asm("mov.b64 {%0, %1}, %2;" : "=f"(r.x), "=f"(r.y) : "l"(v));
    return r;
}
__device__ __forceinline__ float gelu_exact(float v) {
    return 0.5f * v * (1.0f + erff(v * 0.70710678118654752440f));
}

// ---------------- 0: init (zero d_out, slots = -1) ----------------
__global__ void init_kernel(float4* __restrict__ out4) {
    int i = blockIdx.x * 256 + threadIdx.x;          // grid covers TT*DD/4 exactly
    out4[i] = make_float4(0.f, 0.f, 0.f, 0.f);
    if (i < EE * CC) g_tok_of_slot[i] = -1;
}

// ---------------- 1: router (one warp per token) ----------------
__global__ void router_kernel(const float* __restrict__ x,
                              const float* __restrict__ wr,   // [D,E]
                              const float* __restrict__ br) { // [E]
    int gw   = (blockIdx.x * blockDim.x + threadIdx.x) >> 5;
    int lane = threadIdx.x & 31;
    if (gw >= TT) return;
    const float* xt = x + (size_t)gw * DD;

    float acc[EE];
#pragma unroll
    for (int e = 0; e < EE; e++) acc[e] = 0.f;

    for (int d = lane; d < DD; d += 32) {
        float xv = xt[d];
        const float4* w4 = reinterpret_cast<const float4*>(wr + (size_t)d * EE);
        float4 wa = w4[0], wb = w4[1];
        acc[0] += xv * wa.x; acc[1] += xv * wa.y;
        acc[2] += xv * wa.z; acc[3] += xv * wa.w;
        acc[4] += xv * wb.x; acc[5] += xv * wb.y;
        acc[6] += xv * wb.z; acc[7] += xv * wb.w;
    }
#pragma unroll
    for (int e = 0; e < EE; e++)
#pragma unroll
        for (int o = 16; o > 0; o >>= 1)
            acc[e] += __shfl_xor_sync(0xffffffffu, acc[e], o);

    if (lane == 0) {
        float l[EE];
        float best = -1e30f; int bi = 0;
#pragma unroll
        for (int e = 0; e < EE; e++) {
            l[e] = acc[e] + br[e];
            if (l[e] > best) { best = l[e]; bi = e; }   // first-max on ties, like argmax
        }
        float s = 0.f;
#pragma unroll
        for (int e = 0; e < EE; e++) s += expf(l[e] - best);
        g_gate[gw]   = 1.0f / s;   // = max softmax prob
        g_expert[gw] = bi;
    }
}

// ---------------- 2: ordered capacity assignment (single block, ballot scan) ----------------
__global__ void assign_kernel() {
    __shared__ int s_warpcnt[EE][32];
    __shared__ int s_warpoff[EE][32];
    __shared__ int s_chunktot[EE];
    __shared__ int s_base[EE];

    int tid = threadIdx.x, lane = tid & 31, wid = tid >> 5;
    if (tid < EE) s_base[tid] = 0;

    for (int chunk = 0; chunk < TT; chunk += 1024) {
        __syncthreads();                       // protects s_warpcnt reuse + base update
        int t = chunk + tid;
        int e = g_expert[t];
        int inwarp = 0;
#pragma unroll
        for (int ee = 0; ee < EE; ee++) {
            unsigned m = __ballot_sync(0xffffffffu, e == ee);
            if (lane == 0) s_warpcnt[ee][wid] = __popc(m);
            if (e == ee)   inwarp = __popc(m & ((1u << lane) - 1u));
        }
        __syncthreads();
        if (wid < EE) {                        // warp `wid` scans expert `wid`'s 32 warp counts
            int v = s_warpcnt[wid][lane];
            int sc = v;
#pragma unroll
            for (int o = 1; o < 32; o <<= 1) {
                int n = __shfl_up_sync(0xffffffffu, sc, o);
                if (lane >= o) sc += n;
            }
            s_warpoff[wid][lane] = sc - v;     // exclusive
            if (lane == 31) s_chunktot[wid] = sc;
        }
        __syncthreads();
        int pos = s_base[e] + s_warpoff[e][wid] + inwarp + 1;   // 1-based, reference quirk
        if (pos < CC) {
            g_tok_of_slot[e * CC + pos] = t;   // slot 0 never used; 511 kept/expert max
        } else {
            g_gate[t] = 0.f;                   // dropped
        }
        __syncthreads();
        if (tid < EE) s_base[tid] += s_chunktot[tid];
    }
}

// ---------------- 3: dispatch (gate-scaled scatter into [E,C,D]) ----------------
__global__ void dispatch_kernel(const float* __restrict__ x) {
    int slot = blockIdx.x;                       // 0..E*C-1
    int t = g_tok_of_slot[slot];
    float4* dst = reinterpret_cast<float4*>(g_expert_in) + (size_t)slot * (DD / 4) + threadIdx.x;
    if (t < 0) { *dst = make_float4(0.f, 0.f, 0.f, 0.f); return; }
    float g = g_gate[t];
    float4 v = reinterpret_cast<const float4*>(x)[(size_t)t * (DD / 4) + threadIdx.x];
    v.x *= g; v.y *= g; v.z *= g; v.w *= g;
    *dst = v;
}

// ---------------- 4/5: grouped GEMM, fp32 with packed FFMA2 inner loop ----------------
// Tile: 128(M) x 128(N) x 16(K), 256 threads, 8x8 micro-tile (N packed in f32x2 pairs).
// PHASE1: A = g_expert_in[e] [C,D], B = w1[e] [D,F], out = gelu(.+b1) -> g_h
// PHASE2: A = g_h[e] [C,F],      B = w2[e] [F,D], out = gate * (.+b2) scattered to d_out
template <bool PHASE1>
__launch_bounds__(256, 2)
__global__ void moe_gemm(const float* __restrict__ Ball,
                         const float* __restrict__ bias,
                         float* __restrict__ outp) {
    constexpr int K = PHASE1 ? DD : FF;
    constexpr int N = PHASE1 ? FF : DD;

    const int e  = blockIdx.z;
    const int bm = blockIdx.y;
    const int bn = blockIdx.x;

    const float* A = (PHASE1 ? g_expert_in : g_h) + (size_t)e * CC * K;
    const float* B = Ball + (size_t)e * K * N;

    __shared__ float As[2][16][128];   // [k][m]
    __shared__ float Bs[2][16][128];   // [k][n]

    const int tid = threadIdx.x;
    const int tx = tid & 15, ty = tid >> 4;
    const int m0 = ty * 8;

    // global loaders: A tile 128x16 (512 float4, 2/thread), B tile 16x128 (512 float4, 2/thread)
    const int ar0 = tid >> 2;            // 0..63 (second half at +64)
    const int ak0 = (tid & 3) * 4;       // k within tile
    const int bk0 = tid >> 5;            // 0..7  (second half at +8)
    const int bn0 = (tid & 31) * 4;      // 0..124

    const float* Aptr0 = A + (size_t)(bm * 128 + ar0)      * K + ak0;
    const float* Aptr1 = A + (size_t)(bm * 128 + ar0 + 64) * K + ak0;
    const float* Bptr0 = B + (size_t)bk0       * N + bn * 128 + bn0;
    const float* Bptr1 = B + (size_t)(bk0 + 8) * N + bn * 128 + bn0;

    unsigned long long cc[8][4];
#pragma unroll
    for (int i = 0; i < 8; i++)
#pragma unroll
        for (int j = 0; j < 4; j++) cc[i][j] = 0ull;

    // prologue: tile 0
    float4 ra0 = *reinterpret_cast<const float4*>(Aptr0);
    float4 ra1 = *reinterpret_cast<const float4*>(Aptr1);
    float4 rb0 = *reinterpret_cast<const float4*>(Bptr0);
    float4 rb1 = *reinterpret_cast<const float4*>(Bptr1);
    As[0][ak0 + 0][ar0] = ra0.x; As[0][ak0 + 1][ar0] = ra0.y;
    As[0][ak0 + 2][ar0] = ra0.z; As[0][ak0 + 3][ar0] = ra0.w;
    As[0][ak0 + 0][ar0 + 64] = ra1.x; As[0][ak0 + 1][ar0 + 64] = ra1.y;
    As[0][ak0 + 2][ar0 + 64] = ra1.z; As[0][ak0 + 3][ar0 + 64] = ra1.w;
    *reinterpret_cast<float4*>(&Bs[0][bk0][bn0])     = rb0;
    *reinterpret_cast<float4*>(&Bs[0][bk0 + 8][bn0]) = rb1;
    __syncthreads();

    const int tiles = K / 16;
    int cur = 0;
    for (int tile = 0; tile < tiles; tile++) {
        const bool more = (tile + 1 < tiles);
        const int kt = (tile + 1) * 16;
        if (more) {                                 // issue next-tile global loads early
            ra0 = *reinterpret_cast<const float4*>(Aptr0 + kt);
            ra1 = *reinterpret_cast<const float4*>(Aptr1 + kt);
            rb0 = *reinterpret_cast<const float4*>(Bptr0 + (size_t)kt * N);
            rb1 = *reinterpret_cast<const float4*>(Bptr1 + (size_t)kt * N);
        }
#pragma unroll
        for (int kk = 0; kk < 16; kk++) {
            float4 a0 = *reinterpret_cast<const float4*>(&As[cur][kk][m0]);
            float4 a1 = *reinterpret_cast<const float4*>(&As[cur][kk][m0 + 4]);
            ulonglong2 b0 = *reinterpret_cast<const ulonglong2*>(&Bs[cur][kk][tx * 4]);
            ulonglong2 b1 = *reinterpret_cast<const ulonglong2*>(&Bs[cur][kk][64 + tx * 4]);
            unsigned long long av[8];
            av[0] = dup2(a0.x); av[1] = dup2(a0.y); av[2] = dup2(a0.z); av[3] = dup2(a0.w);
            av[4] = dup2(a1.x); av[5] = dup2(a1.y); av[6] = dup2(a1.z); av[7] = dup2(a1.w);
            unsigned long long bp[4] = { b0.x, b0.y, b1.x, b1.y };
#pragma unroll
            for (int i = 0; i < 8; i++)
#pragma unroll
                for (int j = 0; j < 4; j++)
                    ffma2(cc[i][j], av[i], bp[j]);
        }
        if (more) {
            const int nxt = cur ^ 1;
            As[nxt][ak0 + 0][ar0] = ra0.x; As[nxt][ak0 + 1][ar0] = ra0.y;
            As[nxt][ak0 + 2][ar0] = ra0.z; As[nxt][ak0 + 3][ar0] = ra0.w;
            As[nxt][ak0 + 0][ar0 + 64] = ra1.x; As[nxt][ak0 + 1][ar0 + 64] = ra1.y;
            As[nxt][ak0 + 2][ar0 + 64] = ra1.z; As[nxt][ak0 + 3][ar0 + 64] = ra1.w;
            *reinterpret_cast<float4*>(&Bs[nxt][bk0][bn0])     = rb0;
            *reinterpret_cast<float4*>(&Bs[nxt][bk0 + 8][bn0]) = rb1;
        }
        __syncthreads();
        cur ^= 1;
    }

    // ---------------- epilogue ----------------
    const int nb = bn * 128 + tx * 4;                       // n block0 base; block1 at +64
    float4 bias0 = *reinterpret_cast<const float4*>(bias + (size_t)e * N + nb);
    float4 bias1 = *reinterpret_cast<const float4*>(bias + (size_t)e * N + nb + 64);

    if (PHASE1) {
        float* H = g_h + (size_t)e * CC * N;
#pragma unroll
        for (int i = 0; i < 8; i++) {
            int r = bm * 128 + m0 + i;
            float2 p0 = unpk2(cc[i][0]), p1 = unpk2(cc[i][1]);
            float2 p2 = unpk2(cc[i][2]), p3 = unpk2(cc[i][3]);
            float4 v0 = make_float4(gelu_exact(p0.x + bias0.x), gelu_exact(p0.y + bias0.y),
                                    gelu_exact(p1.x + bias0.z), gelu_exact(p1.y + bias0.w));
            float4 v1 = make_float4(gelu_exact(p2.x + bias1.x), gelu_exact(p2.y + bias1.y),
                                    gelu_exact(p3.x + bias1.z), gelu_exact(p3.y + bias1.w));
            *reinterpret_cast<float4*>(H + (size_t)r * N + nb)      = v0;
            *reinterpret_cast<float4*>(H + (size_t)r * N + nb + 64) = v1;
        }
    } else {
#pragma unroll
        for (int i = 0; i < 8; i++) {
            int r = bm * 128 + m0 + i;
            int t = g_tok_of_slot[e * CC + r];
            if (t < 0) continue;                            // empty slot -> contributes nothing
            float g = g_gate[t];
            float2 p0 = unpk2(cc[i][0]), p1 = unpk2(cc[i][1]);
            float2 p2 = unpk2(cc[i][2]), p3 = unpk2(cc[i][3]);
            float4 v0 = make_float4(g * (p0.x + bias0.x), g * (p0.y + bias0.y),
                                    g * (p1.x + bias0.z), g * (p1.y + bias0.w));
            float4 v1 = make_float4(g * (p2.x + bias1.x), g * (p2.y + bias1.y),
                                    g * (p3.x + bias1.z), g * (p3.y + bias1.w));
            *reinterpret_cast<float4*>(outp + (size_t)t * DD + nb)      = v0;
            *reinterpret_cast<float4*>(outp + (size_t)t * DD + nb + 64) = v1;
        }
    }
}

// ---------------- launch ----------------
extern "C" void kernel_launch(void* const* d_in, const int* in_sizes, int n_in,
                              void* d_out, int out_size) {
    (void)in_sizes; (void)n_in; (void)out_size;
    const float* x  = (const float*)d_in[0];   // [B,S,D]
    const float* wr = (const float*)d_in[1];   // [D,E]
    const float* br = (const float*)d_in[2];   // [E]
    const float* w1 = (const float*)d_in[3];   // [E,D,F]
    const float* b1 = (const float*)d_in[4];   // [E,F]
    const float* w2 = (const float*)d_in[5];   // [E,F,D]
    const float* b2 = (const float*)d_in[6];   // [E,D]
    float* out = (float*)d_out;                // [B,S,D] f32

    init_kernel<<<(TT * DD / 4) / 256, 256>>>((float4*)out);
    router_kernel<<<TT / 8, 256>>>(x, wr, br);
    assign_kernel<<<1, 1024>>>();
    dispatch_kernel<<<EE * CC, 256>>>(x);
    moe_gemm<true ><<<dim3(FF / 128, CC / 128, EE), 256>>>(w1, b1, nullptr);
    moe_gemm<false><<<dim3(DD / 128, CC / 128, EE), 256>>>(w2, b2, out);
}

// round 6
// speedup vs baseline: 1.7000x; 1.7000x over previous
#include <cuda_runtime.h>
#include <cuda_bf16.h>
#include <math.h>
#include <stdint.h>

// Problem dims (fixed by the reference)
#define TT 4096   // tokens = B*S
#define DD 1024   // model dim
#define FF 4096   // ffn dim
#define EE 8      // experts
#define CC 512    // capacity

// ---------------- scratch (device globals; no runtime allocation) ----------------
__device__ float g_gate[TT];
__device__ int   g_expert[TT];
__device__ int   g_tok_of_slot[EE * CC];

// __align__(16): accessed via uint2/uint4/cp.async 16B.
__device__ __align__(16) __nv_bfloat16 g_a_hi[EE * CC * DD];
__device__ __align__(16) __nv_bfloat16 g_a_lo[EE * CC * DD];
__device__ __align__(16) __nv_bfloat16 g_w1t_hi[(size_t)EE * FF * DD];  // W1^T [E, F(N), D(K)]
__device__ __align__(16) __nv_bfloat16 g_w1t_lo[(size_t)EE * FF * DD];
__device__ __align__(16) __nv_bfloat16 g_w2t_hi[(size_t)EE * DD * FF];  // W2^T [E, D(N), F(K)]
__device__ __align__(16) __nv_bfloat16 g_w2t_lo[(size_t)EE * DD * FF];
__device__ __align__(16) __nv_bfloat16 g_h_hi[(size_t)EE * CC * FF];    // hidden, hi/lo split
__device__ __align__(16) __nv_bfloat16 g_h_lo[(size_t)EE * CC * FF];

// ---------------- helpers (baseline sm_80+ features only; NO tcgen05) ----------------
__device__ __forceinline__ uint32_t smem_u32(const void* p) {
    uint32_t a;
    asm("{ .reg .u64 t; cvta.to.shared.u64 t, %1; cvt.u32.u64 %0, t; }" : "=r"(a) : "l"(p));
    return a;
}
__device__ __forceinline__ void cp_async16(uint32_t saddr, const void* gaddr) {
    asm volatile("cp.async.cg.shared.global [%0], [%1], 16;" :: "r"(saddr), "l"(gaddr) : "memory");
}
#define CP_COMMIT()  asm volatile("cp.async.commit_group;" ::: "memory")
#define CP_WAIT1()   asm volatile("cp.async.wait_group 1;" ::: "memory")

__device__ __forceinline__ void ldsm_x4(uint32_t* r, uint32_t addr) {
    asm volatile("ldmatrix.sync.aligned.m8n8.x4.shared.b16 {%0,%1,%2,%3}, [%4];"
                 : "=r"(r[0]), "=r"(r[1]), "=r"(r[2]), "=r"(r[3]) : "r"(addr));
}
__device__ __forceinline__ void mma16816(float* c, const uint32_t* a, const uint32_t* b) {
    asm volatile(
        "mma.sync.aligned.m16n8k16.row.col.f32.bf16.bf16.f32 "
        "{%0,%1,%2,%3}, {%4,%5,%6,%7}, {%8,%9}, {%0,%1,%2,%3};"
        : "+f"(c[0]), "+f"(c[1]), "+f"(c[2]), "+f"(c[3])
        : "r"(a[0]), "r"(a[1]), "r"(a[2]), "r"(a[3]), "r"(b[0]), "r"(b[1]));
}
#define SWZ128(o) ((o) ^ (((o) >> 3) & 0x70))

__device__ __forceinline__ float gelu_exact(float v) {
    return 0.5f * v * (1.0f + erff(v * 0.70710678118654752440f));
}

// ---------------- 0: init ----------------
__global__ void init_kernel(float4* __restrict__ out4) {
    int i = blockIdx.x * 256 + threadIdx.x;
    out4[i] = make_float4(0.f, 0.f, 0.f, 0.f);
    if (i < EE * CC) g_tok_of_slot[i] = -1;
}

// ---------------- 1: router (one warp per token) ----------------
__global__ void router_kernel(const float* __restrict__ x,
                              const float* __restrict__ wr,
                              const float* __restrict__ br) {
    int gw = (blockIdx.x * blockDim.x + threadIdx.x) >> 5;
    int lane = threadIdx.x & 31;
    if (gw >= TT) return;
    const float* xt = x + (size_t)gw * DD;
    float acc[EE];
#pragma unroll
    for (int e = 0; e < EE; e++) acc[e] = 0.f;
    for (int d = lane; d < DD; d += 32) {
        float xv = xt[d];
        const float4* w4 = reinterpret_cast<const float4*>(wr + (size_t)d * EE);
        float4 wa = w4[0], wb = w4[1];
        acc[0] += xv * wa.x; acc[1] += xv * wa.y; acc[2] += xv * wa.z; acc[3] += xv * wa.w;
        acc[4] += xv * wb.x; acc[5] += xv * wb.y; acc[6] += xv * wb.z; acc[7] += xv * wb.w;
    }
#pragma unroll
    for (int e = 0; e < EE; e++)
#pragma unroll
        for (int o = 16; o > 0; o >>= 1) acc[e] += __shfl_xor_sync(0xffffffffu, acc[e], o);
    if (lane == 0) {
        float l[EE]; float best = -1e30f; int bi = 0;
#pragma unroll
        for (int e = 0; e < EE; e++) {
            l[e] = acc[e] + br[e];
            if (l[e] > best) { best = l[e]; bi = e; }
        }
        float s = 0.f;
#pragma unroll
        for (int e = 0; e < EE; e++) s += expf(l[e] - best);
        g_gate[gw] = 1.0f / s;
        g_expert[gw] = bi;
    }
}

// ---------------- 2: ordered capacity assignment ----------------
__global__ void assign_kernel() {
    __shared__ int s_warpcnt[EE][32], s_warpoff[EE][32], s_chunktot[EE], s_base[EE];
    int tid = threadIdx.x, lane = tid & 31, wid = tid >> 5;
    if (tid < EE) s_base[tid] = 0;
    for (int chunk = 0; chunk < TT; chunk += 1024) {
        __syncthreads();
        int t = chunk + tid;
        int e = g_expert[t];
        int inwarp = 0;
#pragma unroll
        for (int ee = 0; ee < EE; ee++) {
            unsigned m = __ballot_sync(0xffffffffu, e == ee);
            if (lane == 0) s_warpcnt[ee][wid] = __popc(m);
            if (e == ee) inwarp = __popc(m & ((1u << lane) - 1u));
        }
        __syncthreads();
        if (wid < EE) {
            int v = s_warpcnt[wid][lane], sc = v;
#pragma unroll
            for (int o = 1; o < 32; o <<= 1) {
                int n = __shfl_up_sync(0xffffffffu, sc, o);
                if (lane >= o) sc += n;
            }
            s_warpoff[wid][lane] = sc - v;
            if (lane == 31) s_chunktot[wid] = sc;
        }
        __syncthreads();
        int pos = s_base[e] + s_warpoff[e][wid] + inwarp + 1;  // 1-based (reference quirk)
        if (pos < CC) g_tok_of_slot[e * CC + pos] = t;
        else          g_gate[t] = 0.f;
        __syncthreads();
        if (tid < EE) s_base[tid] += s_chunktot[tid];
    }
}

// ---------------- 3: dispatch -> gate-scaled bf16 hi/lo ----------------
__global__ void dispatch_kernel(const float* __restrict__ x) {
    int slot = blockIdx.x;
    int t = g_tok_of_slot[slot];
    int i = threadIdx.x;                    // 256 threads, 4 elems each
    uint2* dh = reinterpret_cast<uint2*>(g_a_hi + (size_t)slot * DD) + i;
    uint2* dl = reinterpret_cast<uint2*>(g_a_lo + (size_t)slot * DD) + i;
    if (t < 0) { *dh = make_uint2(0u, 0u); *dl = make_uint2(0u, 0u); return; }
    float g = g_gate[t];
    float4 v = reinterpret_cast<const float4*>(x)[(size_t)t * (DD / 4) + i];
    float f[4] = { v.x * g, v.y * g, v.z * g, v.w * g };
    __nv_bfloat16 hi[4], lo[4];
#pragma unroll
    for (int k = 0; k < 4; k++) {
        hi[k] = __float2bfloat16(f[k]);
        lo[k] = __float2bfloat16(f[k] - __bfloat162float(hi[k]));
    }
    __nv_bfloat162 h0(hi[0], hi[1]), h1(hi[2], hi[3]), l0(lo[0], lo[1]), l1(lo[2], lo[3]);
    *dh = make_uint2(*(uint32_t*)&h0, *(uint32_t*)&h1);
    *dl = make_uint2(*(uint32_t*)&l0, *(uint32_t*)&l1);
}

// ---------------- 4: weight transpose + bf16 hi/lo split ----------------
// in: W [E, R, Cn] f32 row-major; out: [E, Cn, R] bf16 hi/lo
__global__ void wsplit_run(const float* __restrict__ Win, int R, int Cn, int which) {
    __shared__ float t[32][33];
    int e = blockIdx.z;
    const float* Wp = Win + (size_t)e * R * Cn;
    int c  = blockIdx.x * 32 + threadIdx.x;
    int r0 = blockIdx.y * 32 + threadIdx.y;
#pragma unroll
    for (int i = 0; i < 4; i++)
        t[threadIdx.y + i * 8][threadIdx.x] = Wp[(size_t)(r0 + i * 8) * Cn + c];
    __syncthreads();
    __nv_bfloat16* hi = which ? g_w1t_hi : g_w2t_hi;
    __nv_bfloat16* lo = which ? g_w1t_lo : g_w2t_lo;
    size_t base = (size_t)e * R * Cn;
    int oc = blockIdx.y * 32 + threadIdx.x;   // k index (orig row)
#pragma unroll
    for (int i = 0; i < 4; i++) {
        int orr = blockIdx.x * 32 + threadIdx.y + i * 8;   // n index (orig col)
        float v = t[threadIdx.x][threadIdx.y + i * 8];
        __nv_bfloat16 h = __float2bfloat16(v);
        float lf = v - __bfloat162float(h);
        hi[base + (size_t)orr * R + oc] = h;
        lo[base + (size_t)orr * R + oc] = __float2bfloat16(lf);
    }
}

// ---------------- 5/6: grouped GEMM via mma.sync bf16 hi/lo split (3 MMAs) --------
// CTA tile 128(M)x128(N), K-chunk 32. 8 warps in 2(M)x4(N); warp tile 64x32.
// SMEM per stage: A 128 rows x 128B (hi cols 0-31, lo cols 32-63 as bf16) = 16KB, B same.
// 3-stage cp.async pipeline, 1 commit-group per stage.
#define NSTAGE  3
#define STAGE_B 32768
#define GEMM_SMEM (NSTAGE * STAGE_B)   // 98304 B

template <int KDIM, int NTOT, bool PHASE1>
__global__ void __launch_bounds__(256, 1)
moe_gemm_mma(const float* __restrict__ bias, float* __restrict__ outp) {
    extern __shared__ __align__(1024) char smem[];
    const uint32_t sbase = smem_u32(smem);
    const int tid = threadIdx.x;
    const int lane = tid & 31, warp = tid >> 5;
    const int wm = warp & 1, wn = warp >> 1;            // warp at (64*wm, 32*wn)
    const int e = blockIdx.z, bm = blockIdx.y, bn = blockIdx.x;

    const __nv_bfloat16* Ah = (PHASE1 ? g_a_hi : g_h_hi) + ((size_t)e * CC + bm * 128) * KDIM;
    const __nv_bfloat16* Al = (PHASE1 ? g_a_lo : g_h_lo) + ((size_t)e * CC + bm * 128) * KDIM;
    const __nv_bfloat16* Bh = (PHASE1 ? g_w1t_hi : g_w2t_hi) + ((size_t)e * NTOT + bn * 128) * KDIM;
    const __nv_bfloat16* Bl = (PHASE1 ? g_w1t_lo : g_w2t_lo) + ((size_t)e * NTOT + bn * 128) * KDIM;

    // ldmatrix lane addressing (constant per thread)
    const uint32_t laneRowA = (lane & 7) + ((lane >> 3) & 1) * 8;   // + i*16 + wm*64
    const uint32_t laneKBA  = ((lane >> 4) & 1) * 16;               // k-byte block
    const uint32_t matB     = lane >> 3;
    const uint32_t laneRowB = (lane & 7) + (matB >> 1) * 8;         // + jp*16 + wn*32
    const uint32_t laneKBB  = (matB & 1) * 16;

    auto issue_stage = [&](int c) {
        const int st = c % NSTAGE;
        const uint32_t ab = sbase + st * STAGE_B;
        const uint32_t bb = ab + 16384;
        const int gk = c * 32;
#pragma unroll
        for (int q = 0; q < 4; q++) {
            int idx = tid + q * 256;                 // 0..1023
            int h = idx >> 9, rem = idx & 511;
            int r = rem >> 2, g = rem & 3;
            size_t go = (size_t)r * KDIM + gk + g * 8;
            uint32_t so = SWZ128((uint32_t)(r * 128 + h * 64 + g * 16));
            cp_async16(ab + so, (h ? Al : Ah) + go);
            cp_async16(bb + so, (h ? Bl : Bh) + go);
        }
        CP_COMMIT();
    };

    float acc[4][4][4];
#pragma unroll
    for (int i = 0; i < 4; i++)
#pragma unroll
        for (int j = 0; j < 4; j++)
#pragma unroll
            for (int q = 0; q < 4; q++) acc[i][j][q] = 0.f;

    issue_stage(0);
    issue_stage(1);

    constexpr int NCH = KDIM / 32;
    for (int c = 0; c < NCH; c++) {
        CP_WAIT1();                 // group c complete (c+2 groups always issued)
        __syncthreads();
        const uint32_t ab = sbase + (c % NSTAGE) * STAGE_B;
        const uint32_t bb = ab + 16384;
#pragma unroll
        for (int s = 0; s < 2; s++) {
            uint32_t bh[4][2], bl[4][2];
#pragma unroll
            for (int jp = 0; jp < 2; jp++) {
                uint32_t rB = wn * 32 + jp * 16 + laneRowB;
                uint32_t r4[4];
                ldsm_x4(r4, bb + SWZ128(rB * 128 + 0  + s * 32 + laneKBB));
                bh[jp * 2][0] = r4[0]; bh[jp * 2][1] = r4[1];
                bh[jp * 2 + 1][0] = r4[2]; bh[jp * 2 + 1][1] = r4[3];
                ldsm_x4(r4, bb + SWZ128(rB * 128 + 64 + s * 32 + laneKBB));
                bl[jp * 2][0] = r4[0]; bl[jp * 2][1] = r4[1];
                bl[jp * 2 + 1][0] = r4[2]; bl[jp * 2 + 1][1] = r4[3];
            }
#pragma unroll
            for (int i = 0; i < 4; i++) {
                uint32_t ah[4], al[4];
                uint32_t rA = wm * 64 + i * 16 + laneRowA;
                ldsm_x4(ah, ab + SWZ128(rA * 128 + 0  + s * 32 + laneKBA));
                ldsm_x4(al, ab + SWZ128(rA * 128 + 64 + s * 32 + laneKBA));
#pragma unroll
                for (int j = 0; j < 4; j++) {
                    mma16816(acc[i][j], ah, bh[j]);
                    mma16816(acc[i][j], ah, bl[j]);
                    mma16816(acc[i][j], al, bh[j]);
                }
            }
        }
        __syncthreads();            // all warps done reading buffer before refill
        if (c + 2 < NCH) issue_stage(c + 2);
        else CP_COMMIT();           // empty group keeps group count monotone
    }

    // ---------------- epilogue ----------------
    float2 bv[4];
#pragma unroll
    for (int j = 0; j < 4; j++) {
        int col = bn * 128 + wn * 32 + j * 8 + (lane & 3) * 2;
        bv[j] = *reinterpret_cast<const float2*>(bias + (size_t)e * NTOT + col);
    }

    if (PHASE1) {
#pragma unroll
        for (int i = 0; i < 4; i++) {
#pragma unroll
            for (int rr = 0; rr < 2; rr++) {
                int row = bm * 128 + wm * 64 + i * 16 + (lane >> 2) + rr * 8;
                size_t ro = ((size_t)e * CC + row) * NTOT;
#pragma unroll
                for (int j = 0; j < 4; j++) {
                    int col = bn * 128 + wn * 32 + j * 8 + (lane & 3) * 2;
                    float v0 = gelu_exact(acc[i][j][rr * 2 + 0] + bv[j].x);
                    float v1 = gelu_exact(acc[i][j][rr * 2 + 1] + bv[j].y);
                    __nv_bfloat16 h0 = __float2bfloat16(v0), h1 = __float2bfloat16(v1);
                    __nv_bfloat16 l0 = __float2bfloat16(v0 - __bfloat162float(h0));
                    __nv_bfloat16 l1 = __float2bfloat16(v1 - __bfloat162float(h1));
                    __nv_bfloat162 hh(h0, h1), ll(l0, l1);
                    *reinterpret_cast<uint32_t*>(g_h_hi + ro + col) = *(uint32_t*)&hh;
                    *reinterpret_cast<uint32_t*>(g_h_lo + ro + col) = *(uint32_t*)&ll;
                }
            }
        }
    } else {
#pragma unroll
        for (int i = 0; i < 4; i++) {
#pragma unroll
            for (int rr = 0; rr < 2; rr++) {
                int row = bm * 128 + wm * 64 + i * 16 + (lane >> 2) + rr * 8;
                int t = g_tok_of_slot[e * CC + row];
                if (t < 0) continue;
                float g = g_gate[t];
#pragma unroll
                for (int j = 0; j < 4; j++) {
                    int col = bn * 128 + wn * 32 + j * 8 + (lane & 3) * 2;
                    float2 v;
                    v.x = g * (acc[i][j][rr * 2 + 0] + bv[j].x);
                    v.y = g * (acc[i][j][rr * 2 + 1] + bv[j].y);
                    *reinterpret_cast<float2*>(outp + (size_t)t * DD + col) = v;
                }
            }
        }
    }
}

// ---------------- launch ----------------
extern "C" void kernel_launch(void* const* d_in, const int* in_sizes, int n_in,
                              void* d_out, int out_size) {
    (void)in_sizes; (void)n_in; (void)out_size;
    const float* x  = (const float*)d_in[0];
    const float* wr = (const float*)d_in[1];
    const float* br = (const float*)d_in[2];
    const float* w1 = (const float*)d_in[3];
    const float* b1 = (const float*)d_in[4];
    const float* w2 = (const float*)d_in[5];
    const float* b2 = (const float*)d_in[6];
    float* out = (float*)d_out;

    cudaFuncSetAttribute(moe_gemm_mma<DD, FF, true>,
                         cudaFuncAttributeMaxDynamicSharedMemorySize, GEMM_SMEM);
    cudaFuncSetAttribute(moe_gemm_mma<FF, DD, false>,
                         cudaFuncAttributeMaxDynamicSharedMemorySize, GEMM_SMEM);

    init_kernel<<<(TT * DD / 4) / 256, 256>>>((float4*)out);
    router_kernel<<<TT / 8, 256>>>(x, wr, br);
    assign_kernel<<<1, 1024>>>();
    dispatch_kernel<<<EE * CC, 256>>>(x);
    // W1 [E, D, F] -> g_w1t [E, F, D]
    wsplit_run<<<dim3(FF / 32, DD / 32, EE), dim3(32, 8)>>>(w1, DD, FF, 1);
    // W2 [E, F, D] -> g_w2t [E, D, F]
    wsplit_run<<<dim3(DD / 32, FF / 32, EE), dim3(32, 8)>>>(w2, FF, DD, 0);
    moe_gemm_mma<DD, FF, true ><<<dim3(FF / 128, CC / 128, EE), 256, GEMM_SMEM>>>(b1, nullptr);
    moe_gemm_mma<FF, DD, false><<<dim3(DD / 128, CC / 128, EE), 256, GEMM_SMEM>>>(b2, out);
}

// round 7
// speedup vs baseline: 1.7523x; 1.0308x over previous
#include <cuda_runtime.h>
#include <cuda_bf16.h>
#include <math.h>
#include <stdint.h>

// Problem dims (fixed by the reference)
#define TT 4096   // tokens = B*S
#define DD 1024   // model dim
#define FF 4096   // ffn dim
#define EE 8      // experts
#define CC 512    // capacity

// ---------------- scratch (device globals; no runtime allocation) ----------------
__device__ float g_gate[TT];
__device__ int   g_expert[TT];
__device__ int   g_tok_of_slot[EE * CC];

// __align__(16): accessed via uint2/uint4/cp.async 16B.
__device__ __align__(16) __nv_bfloat16 g_a_hi[EE * CC * DD];
__device__ __align__(16) __nv_bfloat16 g_a_lo[EE * CC * DD];
__device__ __align__(16) __nv_bfloat16 g_w1t_hi[(size_t)EE * FF * DD];  // W1^T [E, F(N), D(K)]
__device__ __align__(16) __nv_bfloat16 g_w1t_lo[(size_t)EE * FF * DD];
__device__ __align__(16) __nv_bfloat16 g_w2t_hi[(size_t)EE * DD * FF];  // W2^T [E, D(N), F(K)]
__device__ __align__(16) __nv_bfloat16 g_w2t_lo[(size_t)EE * DD * FF];
__device__ __align__(16) __nv_bfloat16 g_h_hi[(size_t)EE * CC * FF];    // hidden, hi/lo split
__device__ __align__(16) __nv_bfloat16 g_h_lo[(size_t)EE * CC * FF];

// ---------------- helpers (baseline sm_80+ features only) ----------------
__device__ __forceinline__ uint32_t smem_u32(const void* p) {
    uint32_t a;
    asm("{ .reg .u64 t; cvta.to.shared.u64 t, %1; cvt.u32.u64 %0, t; }" : "=r"(a) : "l"(p));
    return a;
}
__device__ __forceinline__ void cp_async16(uint32_t saddr, const void* gaddr) {
    asm volatile("cp.async.cg.shared.global [%0], [%1], 16;" :: "r"(saddr), "l"(gaddr) : "memory");
}
#define CP_COMMIT()  asm volatile("cp.async.commit_group;" ::: "memory")
#define CP_WAIT2()   asm volatile("cp.async.wait_group 2;" ::: "memory")

__device__ __forceinline__ void ldsm_x4(uint32_t* r, uint32_t addr) {
    asm volatile("ldmatrix.sync.aligned.m8n8.x4.shared.b16 {%0,%1,%2,%3}, [%4];"
                 : "=r"(r[0]), "=r"(r[1]), "=r"(r[2]), "=r"(r[3]) : "r"(addr));
}
__device__ __forceinline__ void mma16816(float* c, const uint32_t* a, const uint32_t* b) {
    asm volatile(
        "mma.sync.aligned.m16n8k16.row.col.f32.bf16.bf16.f32 "
        "{%0,%1,%2,%3}, {%4,%5,%6,%7}, {%8,%9}, {%0,%1,%2,%3};"
        : "+f"(c[0]), "+f"(c[1]), "+f"(c[2]), "+f"(c[3])
        : "r"(a[0]), "r"(a[1]), "r"(a[2]), "r"(a[3]), "r"(b[0]), "r"(b[1]));
}
#define SWZ128(o) ((o) ^ (((o) >> 3) & 0x70))

__device__ __forceinline__ float gelu_exact(float v) {
    return 0.5f * v * (1.0f + erff(v * 0.70710678118654752440f));
}

// ---------------- 0: init ----------------
__global__ void init_kernel(float4* __restrict__ out4) {
    int i = blockIdx.x * 256 + threadIdx.x;
    out4[i] = make_float4(0.f, 0.f, 0.f, 0.f);
    if (i < EE * CC) g_tok_of_slot[i] = -1;
}

// ---------------- 1: router (one warp per token) ----------------
__global__ void router_kernel(const float* __restrict__ x,
                              const float* __restrict__ wr,
                              const float* __restrict__ br) {
    int gw = (blockIdx.x * blockDim.x + threadIdx.x) >> 5;
    int lane = threadIdx.x & 31;
    if (gw >= TT) return;
    const float* xt = x + (size_t)gw * DD;
    float acc[EE];
#pragma unroll
    for (int e = 0; e < EE; e++) acc[e] = 0.f;
    for (int d = lane; d < DD; d += 32) {
        float xv = xt[d];
        const float4* w4 = reinterpret_cast<const float4*>(wr + (size_t)d * EE);
        float4 wa = w4[0], wb = w4[1];
        acc[0] += xv * wa.x; acc[1] += xv * wa.y; acc[2] += xv * wa.z; acc[3] += xv * wa.w;
        acc[4] += xv * wb.x; acc[5] += xv * wb.y; acc[6] += xv * wb.z; acc[7] += xv * wb.w;
    }
#pragma unroll
    for (int e = 0; e < EE; e++)
#pragma unroll
        for (int o = 16; o > 0; o >>= 1) acc[e] += __shfl_xor_sync(0xffffffffu, acc[e], o);
    if (lane == 0) {
        float l[EE]; float best = -1e30f; int bi = 0;
#pragma unroll
        for (int e = 0; e < EE; e++) {
            l[e] = acc[e] + br[e];
            if (l[e] > best) { best = l[e]; bi = e; }
        }
        float s = 0.f;
#pragma unroll
        for (int e = 0; e < EE; e++) s += expf(l[e] - best);
        g_gate[gw] = 1.0f / s;
        g_expert[gw] = bi;
    }
}

// ---------------- 2: ordered capacity assignment ----------------
__global__ void assign_kernel() {
    __shared__ int s_warpcnt[EE][32], s_warpoff[EE][32], s_chunktot[EE], s_base[EE];
    int tid = threadIdx.x, lane = tid & 31, wid = tid >> 5;
    if (tid < EE) s_base[tid] = 0;
    for (int chunk = 0; chunk < TT; chunk += 1024) {
        __syncthreads();
        int t = chunk + tid;
        int e = g_expert[t];
        int inwarp = 0;
#pragma unroll
        for (int ee = 0; ee < EE; ee++) {
            unsigned m = __ballot_sync(0xffffffffu, e == ee);
            if (lane == 0) s_warpcnt[ee][wid] = __popc(m);
            if (e == ee) inwarp = __popc(m & ((1u << lane) - 1u));
        }
        __syncthreads();
        if (wid < EE) {
            int v = s_warpcnt[wid][lane], sc = v;
#pragma unroll
            for (int o = 1; o < 32; o <<= 1) {
                int n = __shfl_up_sync(0xffffffffu, sc, o);
                if (lane >= o) sc += n;
            }
            s_warpoff[wid][lane] = sc - v;
            if (lane == 31) s_chunktot[wid] = sc;
        }
        __syncthreads();
        int pos = s_base[e] + s_warpoff[e][wid] + inwarp + 1;  // 1-based (reference quirk)
        if (pos < CC) g_tok_of_slot[e * CC + pos] = t;
        else          g_gate[t] = 0.f;
        __syncthreads();
        if (tid < EE) s_base[tid] += s_chunktot[tid];
    }
}

// ---------------- 3: dispatch -> gate-scaled bf16 hi/lo ----------------
__global__ void dispatch_kernel(const float* __restrict__ x) {
    int slot = blockIdx.x;
    int t = g_tok_of_slot[slot];
    int i = threadIdx.x;                    // 256 threads, 4 elems each
    uint2* dh = reinterpret_cast<uint2*>(g_a_hi + (size_t)slot * DD) + i;
    uint2* dl = reinterpret_cast<uint2*>(g_a_lo + (size_t)slot * DD) + i;
    if (t < 0) { *dh = make_uint2(0u, 0u); *dl = make_uint2(0u, 0u); return; }
    float g = g_gate[t];
    float4 v = reinterpret_cast<const float4*>(x)[(size_t)t * (DD / 4) + i];
    float f[4] = { v.x * g, v.y * g, v.z * g, v.w * g };
    __nv_bfloat16 hi[4], lo[4];
#pragma unroll
    for (int k = 0; k < 4; k++) {
        hi[k] = __float2bfloat16(f[k]);
        lo[k] = __float2bfloat16(f[k] - __bfloat162float(hi[k]));
    }
    __nv_bfloat162 h0(hi[0], hi[1]), h1(hi[2], hi[3]), l0(lo[0], lo[1]), l1(lo[2], lo[3]);
    *dh = make_uint2(*(uint32_t*)&h0, *(uint32_t*)&h1);
    *dl = make_uint2(*(uint32_t*)&l0, *(uint32_t*)&l1);
}

// ---------------- 4: weight transpose + bf16 hi/lo split ----------------
// in: W [E, R, Cn] f32 row-major; out: [E, Cn, R] bf16 hi/lo
__global__ void wsplit_run(const float* __restrict__ Win, int R, int Cn, int which) {
    __shared__ float t[32][33];
    int e = blockIdx.z;
    const float* Wp = Win + (size_t)e * R * Cn;
    int c  = blockIdx.x * 32 + threadIdx.x;
    int r0 = blockIdx.y * 32 + threadIdx.y;
#pragma unroll
    for (int i = 0; i < 4; i++)
        t[threadIdx.y + i * 8][threadIdx.x] = Wp[(size_t)(r0 + i * 8) * Cn + c];
    __syncthreads();
    __nv_bfloat16* hi = which ? g_w1t_hi : g_w2t_hi;
    __nv_bfloat16* lo = which ? g_w1t_lo : g_w2t_lo;
    size_t base = (size_t)e * R * Cn;
    int oc = blockIdx.y * 32 + threadIdx.x;   // k index (orig row)
#pragma unroll
    for (int i = 0; i < 4; i++) {
        int orr = blockIdx.x * 32 + threadIdx.y + i * 8;   // n index (orig col)
        float v = t[threadIdx.x][threadIdx.y + i * 8];
        __nv_bfloat16 h = __float2bfloat16(v);
        float lf = v - __bfloat162float(h);
        hi[base + (size_t)orr * R + oc] = h;
        lo[base + (size_t)orr * R + oc] = __float2bfloat16(lf);
    }
}

// ---------------- 5/6: grouped GEMM via mma.sync bf16 hi/lo split (3 MMAs) --------
// CTA tile 128(M)x128(N), K-chunk 32. 8 warps in 2(M)x4(N); warp tile 64x32.
// 4-stage cp.async ring, wait_group 2 => ~2.5 chunks of load lookahead.
// ONE barrier per chunk: with 4 stages, stage (c+3)%4 == (c-1)%4 was last read in
// compute(c-1); the top-of-loop barrier proves all warps finished iteration c-1,
// so issuing into it right after that barrier is race-free.
#define NSTAGE  4
#define STAGE_B 32768
#define GEMM_SMEM (NSTAGE * STAGE_B)   // 131072 B

template <int KDIM, int NTOT, bool PHASE1>
__global__ void __launch_bounds__(256, 1)
moe_gemm_mma(const float* __restrict__ bias, float* __restrict__ outp) {
    extern __shared__ __align__(1024) char smem[];
    const uint32_t sbase = smem_u32(smem);
    const int tid = threadIdx.x;
    const int lane = tid & 31, warp = tid >> 5;
    const int wm = warp & 1, wn = warp >> 1;            // warp at (64*wm, 32*wn)
    const int e = blockIdx.z, bm = blockIdx.y, bn = blockIdx.x;

    const __nv_bfloat16* Ah = (PHASE1 ? g_a_hi : g_h_hi) + ((size_t)e * CC + bm * 128) * KDIM;
    const __nv_bfloat16* Al = (PHASE1 ? g_a_lo : g_h_lo) + ((size_t)e * CC + bm * 128) * KDIM;
    const __nv_bfloat16* Bh = (PHASE1 ? g_w1t_hi : g_w2t_hi) + ((size_t)e * NTOT + bn * 128) * KDIM;
    const __nv_bfloat16* Bl = (PHASE1 ? g_w1t_lo : g_w2t_lo) + ((size_t)e * NTOT + bn * 128) * KDIM;

    // ldmatrix lane addressing (constant per thread)
    const uint32_t laneRowA = (lane & 7) + ((lane >> 3) & 1) * 8;   // + i*16 + wm*64
    const uint32_t laneKBA  = ((lane >> 4) & 1) * 16;               // k-byte block
    const uint32_t matB     = lane >> 3;
    const uint32_t laneRowB = (lane & 7) + (matB >> 1) * 8;         // + jp*16 + wn*32
    const uint32_t laneKBB  = (matB & 1) * 16;

    auto issue_stage = [&](int c) {
        const int st = c % NSTAGE;
        const uint32_t ab = sbase + st * STAGE_B;
        const uint32_t bb = ab + 16384;
        const int gk = c * 32;
#pragma unroll
        for (int q = 0; q < 4; q++) {
            int idx = tid + q * 256;                 // 0..1023
            int h = idx >> 9, rem = idx & 511;
            int r = rem >> 2, g = rem & 3;
            size_t go = (size_t)r * KDIM + gk + g * 8;
            uint32_t so = SWZ128((uint32_t)(r * 128 + h * 64 + g * 16));
            cp_async16(ab + so, (h ? Al : Ah) + go);
            cp_async16(bb + so, (h ? Bl : Bh) + go);
        }
        CP_COMMIT();
    };

    float acc[4][4][4];
#pragma unroll
    for (int i = 0; i < 4; i++)
#pragma unroll
        for (int j = 0; j < 4; j++)
#pragma unroll
            for (int q = 0; q < 4; q++) acc[i][j][q] = 0.f;

    issue_stage(0);
    issue_stage(1);
    issue_stage(2);

    constexpr int NCH = KDIM / 32;
    for (int c = 0; c < NCH; c++) {
        CP_WAIT2();                 // groups issued: 0..c+2 -> pending<=2 means group c done
        __syncthreads();            // visibility of other threads' cp.async data
        if (c + 3 < NCH) issue_stage(c + 3);   // into stage (c-1)%4: safe (see header comment)
        else CP_COMMIT();                       // empty group keeps counts monotone
        const uint32_t ab = sbase + (c % NSTAGE) * STAGE_B;
        const uint32_t bb = ab + 16384;
#pragma unroll
        for (int s = 0; s < 2; s++) {
            uint32_t bh[4][2], bl[4][2];
#pragma unroll
            for (int jp = 0; jp < 2; jp++) {
                uint32_t rB = wn * 32 + jp * 16 + laneRowB;
                uint32_t r4[4];
                ldsm_x4(r4, bb + SWZ128(rB * 128 + 0  + s * 32 + laneKBB));
                bh[jp * 2][0] = r4[0]; bh[jp * 2][1] = r4[1];
                bh[jp * 2 + 1][0] = r4[2]; bh[jp * 2 + 1][1] = r4[3];
                ldsm_x4(r4, bb + SWZ128(rB * 128 + 64 + s * 32 + laneKBB));
                bl[jp * 2][0] = r4[0]; bl[jp * 2][1] = r4[1];
                bl[jp * 2 + 1][0] = r4[2]; bl[jp * 2 + 1][1] = r4[3];
            }
#pragma unroll
            for (int i = 0; i < 4; i++) {
                uint32_t ah[4], al[4];
                uint32_t rA = wm * 64 + i * 16 + laneRowA;
                ldsm_x4(ah, ab + SWZ128(rA * 128 + 0  + s * 32 + laneKBA));
                ldsm_x4(al, ab + SWZ128(rA * 128 + 64 + s * 32 + laneKBA));
#pragma unroll
                for (int j = 0; j < 4; j++) {
                    mma16816(acc[i][j], ah, bh[j]);
                    mma16816(acc[i][j], ah, bl[j]);
                    mma16816(acc[i][j], al, bh[j]);
                }
            }
        }
        // no trailing barrier: next iteration's top barrier provides it
    }

    // ---------------- epilogue ----------------
    float2 bv[4];
#pragma unroll
    for (int j = 0; j < 4; j++) {
        int col = bn * 128 + wn * 32 + j * 8 + (lane & 3) * 2;
        bv[j] = *reinterpret_cast<const float2*>(bias + (size_t)e * NTOT + col);
    }

    if (PHASE1) {
#pragma unroll
        for (int i = 0; i < 4; i++) {
#pragma unroll
            for (int rr = 0; rr < 2; rr++) {
                int row = bm * 128 + wm * 64 + i * 16 + (lane >> 2) + rr * 8;
                size_t ro = ((size_t)e * CC + row) * NTOT;
#pragma unroll
                for (int j = 0; j < 4; j++) {
                    int col = bn * 128 + wn * 32 + j * 8 + (lane & 3) * 2;
                    float v0 = gelu_exact(acc[i][j][rr * 2 + 0] + bv[j].x);
                    float v1 = gelu_exact(acc[i][j][rr * 2 + 1] + bv[j].y);
                    __nv_bfloat16 h0 = __float2bfloat16(v0), h1 = __float2bfloat16(v1);
                    __nv_bfloat16 l0 = __float2bfloat16(v0 - __bfloat162float(h0));
                    __nv_bfloat16 l1 = __float2bfloat16(v1 - __bfloat162float(h1));
                    __nv_bfloat162 hh(h0, h1), ll(l0, l1);
                    *reinterpret_cast<uint32_t*>(g_h_hi + ro + col) = *(uint32_t*)&hh;
                    *reinterpret_cast<uint32_t*>(g_h_lo + ro + col) = *(uint32_t*)&ll;
                }
            }
        }
    } else {
#pragma unroll
        for (int i = 0; i < 4; i++) {
#pragma unroll
            for (int rr = 0; rr < 2; rr++) {
                int row = bm * 128 + wm * 64 + i * 16 + (lane >> 2) + rr * 8;
                int t = g_tok_of_slot[e * CC + row];
                if (t < 0) continue;
                float g = g_gate[t];
#pragma unroll
                for (int j = 0; j < 4; j++) {
                    int col = bn * 128 + wn * 32 + j * 8 + (lane & 3) * 2;
                    float2 v;
                    v.x = g * (acc[i][j][rr * 2 + 0] + bv[j].x);
                    v.y = g * (acc[i][j][rr * 2 + 1] + bv[j].y);
                    *reinterpret_cast<float2*>(outp + (size_t)t * DD + col) = v;
                }
            }
        }
    }
}

// ---------------- launch ----------------
extern "C" void kernel_launch(void* const* d_in, const int* in_sizes, int n_in,
                              void* d_out, int out_size) {
    (void)in_sizes; (void)n_in; (void)out_size;
    const float* x  = (const float*)d_in[0];
    const float* wr = (const float*)d_in[1];
    const float* br = (const float*)d_in[2];
    const float* w1 = (const float*)d_in[3];
    const float* b1 = (const float*)d_in[4];
    const float* w2 = (const float*)d_in[5];
    const float* b2 = (const float*)d_in[6];
    float* out = (float*)d_out;

    cudaFuncSetAttribute(moe_gemm_mma<DD, FF, true>,
                         cudaFuncAttributeMaxDynamicSharedMemorySize, GEMM_SMEM);
    cudaFuncSetAttribute(moe_gemm_mma<FF, DD, false>,
                         cudaFuncAttributeMaxDynamicSharedMemorySize, GEMM_SMEM);

    init_kernel<<<(TT * DD / 4) / 256, 256>>>((float4*)out);
    router_kernel<<<TT / 8, 256>>>(x, wr, br);
    assign_kernel<<<1, 1024>>>();
    dispatch_kernel<<<EE * CC, 256>>>(x);
    // W1 [E, D, F] -> g_w1t [E, F, D]
    wsplit_run<<<dim3(FF / 32, DD / 32, EE), dim3(32, 8)>>>(w1, DD, FF, 1);
    // W2 [E, F, D] -> g_w2t [E, D, F]
    wsplit_run<<<dim3(DD / 32, FF / 32, EE), dim3(32, 8)>>>(w2, FF, DD, 0);
    moe_gemm_mma<DD, FF, true ><<<dim3(FF / 128, CC / 128, EE), 256, GEMM_SMEM>>>(b1, nullptr);
    moe_gemm_mma<FF, DD, false><<<dim3(DD / 128, CC / 128, EE), 256, GEMM_SMEM>>>(b2, out);
}

// round 9
// speedup vs baseline: 1.9426x; 1.1086x over previous
#include <cuda_runtime.h>
#include <cuda_bf16.h>
#include <math.h>
#include <stdint.h>

// Problem dims (fixed by the reference)
#define TT 4096   // tokens = B*S
#define DD 1024   // model dim
#define FF 4096   // ffn dim
#define EE 8      // experts
#define CC 512    // capacity

// ---------------- scratch (device globals; no runtime allocation) ----------------
__device__ float g_gate[TT];
__device__ int   g_expert[TT];
__device__ int   g_tok_of_slot[EE * CC];

// __align__(16): accessed via uint2/uint4/cp.async 16B.
__device__ __align__(16) __nv_bfloat16 g_a_hi[EE * CC * DD];
__device__ __align__(16) __nv_bfloat16 g_a_lo[EE * CC * DD];
__device__ __align__(16) __nv_bfloat16 g_w1t_hi[(size_t)EE * FF * DD];  // W1^T [E, F(N), D(K)]
__device__ __align__(16) __nv_bfloat16 g_w1t_lo[(size_t)EE * FF * DD];
__device__ __align__(16) __nv_bfloat16 g_w2t_hi[(size_t)EE * DD * FF];  // W2^T [E, D(N), F(K)]
__device__ __align__(16) __nv_bfloat16 g_w2t_lo[(size_t)EE * DD * FF];
__device__ __align__(16) __nv_bfloat16 g_h_hi[(size_t)EE * CC * FF];    // hidden, hi/lo split
__device__ __align__(16) __nv_bfloat16 g_h_lo[(size_t)EE * CC * FF];

// ---------------- helpers (baseline sm_80+ features only) ----------------
__device__ __forceinline__ uint32_t smem_u32(const void* p) {
    uint32_t a;
    asm("{ .reg .u64 t; cvta.to.shared.u64 t, %1; cvt.u32.u64 %0, t; }" : "=r"(a) : "l"(p));
    return a;
}
__device__ __forceinline__ void cp_async16(uint32_t saddr, const void* gaddr) {
    asm volatile("cp.async.cg.shared.global [%0], [%1], 16;" :: "r"(saddr), "l"(gaddr) : "memory");
}
#define CP_COMMIT()  asm volatile("cp.async.commit_group;" ::: "memory")
#define CP_WAIT1()   asm volatile("cp.async.wait_group 1;" ::: "memory")

__device__ __forceinline__ void ldsm_x4(uint32_t* r, uint32_t addr) {
    asm volatile("ldmatrix.sync.aligned.m8n8.x4.shared.b16 {%0,%1,%2,%3}, [%4];"
                 : "=r"(r[0]), "=r"(r[1]), "=r"(r[2]), "=r"(r[3]) : "r"(addr));
}
__device__ __forceinline__ void mma16816(float* c, const uint32_t* a, const uint32_t* b) {
    asm volatile(
        "mma.sync.aligned.m16n8k16.row.col.f32.bf16.bf16.f32 "
        "{%0,%1,%2,%3}, {%4,%5,%6,%7}, {%8,%9}, {%0,%1,%2,%3};"
        : "+f"(c[0]), "+f"(c[1]), "+f"(c[2]), "+f"(c[3])
        : "r"(a[0]), "r"(a[1]), "r"(a[2]), "r"(a[3]), "r"(b[0]), "r"(b[1]));
}
#define SWZ128(o) ((o) ^ (((o) >> 3) & 0x70))

__device__ __forceinline__ float gelu_exact(float v) {
    return 0.5f * v * (1.0f + erff(v * 0.70710678118654752440f));
}

// ---------------- 0: init ----------------
__global__ void init_kernel(float4* __restrict__ out4) {
    int i = blockIdx.x * 256 + threadIdx.x;
    out4[i] = make_float4(0.f, 0.f, 0.f, 0.f);
    if (i < EE * CC) g_tok_of_slot[i] = -1;
}

// ---------------- 1: router (one warp per token) ----------------
__global__ void router_kernel(const float* __restrict__ x,
                              const float* __restrict__ wr,
                              const float* __restrict__ br) {
    int gw = (blockIdx.x * blockDim.x + threadIdx.x) >> 5;
    int lane = threadIdx.x & 31;
    if (gw >= TT) return;
    const float* xt = x + (size_t)gw * DD;
    float acc[EE];
#pragma unroll
    for (int e = 0; e < EE; e++) acc[e] = 0.f;
    for (int d = lane; d < DD; d += 32) {
        float xv = xt[d];
        const float4* w4 = reinterpret_cast<const float4*>(wr + (size_t)d * EE);
        float4 wa = w4[0], wb = w4[1];
        acc[0] += xv * wa.x; acc[1] += xv * wa.y; acc[2] += xv * wa.z; acc[3] += xv * wa.w;
        acc[4] += xv * wb.x; acc[5] += xv * wb.y; acc[6] += xv * wb.z; acc[7] += xv * wb.w;
    }
#pragma unroll
    for (int e = 0; e < EE; e++)
#pragma unroll
        for (int o = 16; o > 0; o >>= 1) acc[e] += __shfl_xor_sync(0xffffffffu, acc[e], o);
    if (lane == 0) {
        float l[EE]; float best = -1e30f; int bi = 0;
#pragma unroll
        for (int e = 0; e < EE; e++) {
            l[e] = acc[e] + br[e];
            if (l[e] > best) { best = l[e]; bi = e; }
        }
        float s = 0.f;
#pragma unroll
        for (int e = 0; e < EE; e++) s += expf(l[e] - best);
        g_gate[gw] = 1.0f / s;
        g_expert[gw] = bi;
    }
}

// ---------------- 2: ordered capacity assignment ----------------
__global__ void assign_kernel() {
    __shared__ int s_warpcnt[EE][32], s_warpoff[EE][32], s_chunktot[EE], s_base[EE];
    int tid = threadIdx.x, lane = tid & 31, wid = tid >> 5;
    if (tid < EE) s_base[tid] = 0;
    for (int chunk = 0; chunk < TT; chunk += 1024) {
        __syncthreads();
        int t = chunk + tid;
        int e = g_expert[t];
        int inwarp = 0;
#pragma unroll
        for (int ee = 0; ee < EE; ee++) {
            unsigned m = __ballot_sync(0xffffffffu, e == ee);
            if (lane == 0) s_warpcnt[ee][wid] = __popc(m);
            if (e == ee) inwarp = __popc(m & ((1u << lane) - 1u));
        }
        __syncthreads();
        if (wid < EE) {
            int v = s_warpcnt[wid][lane], sc = v;
#pragma unroll
            for (int o = 1; o < 32; o <<= 1) {
                int n = __shfl_up_sync(0xffffffffu, sc, o);
                if (lane >= o) sc += n;
            }
            s_warpoff[wid][lane] = sc - v;
            if (lane == 31) s_chunktot[wid] = sc;
        }
        __syncthreads();
        int pos = s_base[e] + s_warpoff[e][wid] + inwarp + 1;  // 1-based (reference quirk)
        if (pos < CC) g_tok_of_slot[e * CC + pos] = t;
        else          g_gate[t] = 0.f;
        __syncthreads();
        if (tid < EE) s_base[tid] += s_chunktot[tid];
    }
}

// ---------------- 3: dispatch -> gate-scaled bf16 hi/lo ----------------
__global__ void dispatch_kernel(const float* __restrict__ x) {
    int slot = blockIdx.x;
    int t = g_tok_of_slot[slot];
    int i = threadIdx.x;                    // 256 threads, 4 elems each
    uint2* dh = reinterpret_cast<uint2*>(g_a_hi + (size_t)slot * DD) + i;
    uint2* dl = reinterpret_cast<uint2*>(g_a_lo + (size_t)slot * DD) + i;
    if (t < 0) { *dh = make_uint2(0u, 0u); *dl = make_uint2(0u, 0u); return; }
    float g = g_gate[t];
    float4 v = reinterpret_cast<const float4*>(x)[(size_t)t * (DD / 4) + i];
    float f[4] = { v.x * g, v.y * g, v.z * g, v.w * g };
    __nv_bfloat16 hi[4], lo[4];
#pragma unroll
    for (int k = 0; k < 4; k++) {
        hi[k] = __float2bfloat16(f[k]);
        lo[k] = __float2bfloat16(f[k] - __bfloat162float(hi[k]));
    }
    __nv_bfloat162 h0(hi[0], hi[1]), h1(hi[2], hi[3]), l0(lo[0], lo[1]), l1(lo[2], lo[3]);
    *dh = make_uint2(*(uint32_t*)&h0, *(uint32_t*)&h1);
    *dl = make_uint2(*(uint32_t*)&l0, *(uint32_t*)&l1);
}

// ---------------- 4: weight transpose + bf16 hi/lo split ----------------
// in: W [E, R, Cn] f32 row-major; out: [E, Cn, R] bf16 hi/lo
__global__ void wsplit_run(const float* __restrict__ Win, int R, int Cn, int which) {
    __shared__ float t[32][33];
    int e = blockIdx.z;
    const float* Wp = Win + (size_t)e * R * Cn;
    int c  = blockIdx.x * 32 + threadIdx.x;
    int r0 = blockIdx.y * 32 + threadIdx.y;
#pragma unroll
    for (int i = 0; i < 4; i++)
        t[threadIdx.y + i * 8][threadIdx.x] = Wp[(size_t)(r0 + i * 8) * Cn + c];
    __syncthreads();
    __nv_bfloat16* hi = which ? g_w1t_hi : g_w2t_hi;
    __nv_bfloat16* lo = which ? g_w1t_lo : g_w2t_lo;
    size_t base = (size_t)e * R * Cn;
    int oc = blockIdx.y * 32 + threadIdx.x;   // k index (orig row)
#pragma unroll
    for (int i = 0; i < 4; i++) {
        int orr = blockIdx.x * 32 + threadIdx.y + i * 8;   // n index (orig col)
        float v = t[threadIdx.x][threadIdx.y + i * 8];
        __nv_bfloat16 h = __float2bfloat16(v);
        float lf = v - __bfloat162float(h);
        hi[base + (size_t)orr * R + oc] = h;
        lo[base + (size_t)orr * R + oc] = __float2bfloat16(lf);
    }
}

// ---------------- 5/6: grouped GEMM via mma.sync bf16 hi/lo split (3 MMAs) --------
// CTA tile 128(M)x128(N), K-chunk 32. 8 warps in 2(M)x4(N); warp tile 64x32.
// NSTAGE=3 (96KB) + __launch_bounds__(256,2): TWO CTAs per SM (4 warps/SMSP) for
// cross-CTA latency hiding of LDSM->HMMA chains. Single barrier per chunk; at top
// of iter c, stage (c+2)%3 == (c-1)%3 was last read in iter c-1, which the barrier
// proves complete, so issuing into it is race-free. In-flight stage (c+1)%3 and
// compute stage c%3 are distinct from both.
#define NSTAGE  3
#define STAGE_B 32768
#define GEMM_SMEM (NSTAGE * STAGE_B)   // 98304 B -> 2 CTAs/SM needs 196KB: fits

template <int KDIM, int NTOT, bool PHASE1>
__global__ void __launch_bounds__(256, 2)
moe_gemm_mma(const float* __restrict__ bias, float* __restrict__ outp) {
    extern __shared__ __align__(1024) char smem[];
    const uint32_t sbase = smem_u32(smem);
    const int tid = threadIdx.x;
    const int lane = tid & 31, warp = tid >> 5;
    const int wm = warp & 1, wn = warp >> 1;            // warp at (64*wm, 32*wn)
    const int e = blockIdx.z, bm = blockIdx.y, bn = blockIdx.x;

    const __nv_bfloat16* Ah = (PHASE1 ? g_a_hi : g_h_hi) + ((size_t)e * CC + bm * 128) * KDIM;
    const __nv_bfloat16* Al = (PHASE1 ? g_a_lo : g_h_lo) + ((size_t)e * CC + bm * 128) * KDIM;
    const __nv_bfloat16* Bh = (PHASE1 ? g_w1t_hi : g_w2t_hi) + ((size_t)e * NTOT + bn * 128) * KDIM;
    const __nv_bfloat16* Bl = (PHASE1 ? g_w1t_lo : g_w2t_lo) + ((size_t)e * NTOT + bn * 128) * KDIM;

    // ldmatrix lane addressing (constant per thread)
    const uint32_t laneRowA = (lane & 7) + ((lane >> 3) & 1) * 8;   // + i*16 + wm*64
    const uint32_t laneKBA  = ((lane >> 4) & 1) * 16;               // k-byte block
    const uint32_t matB     = lane >> 3;
    const uint32_t laneRowB = (lane & 7) + (matB >> 1) * 8;         // + jp*16 + wn*32
    const uint32_t laneKBB  = (matB & 1) * 16;

    auto issue_stage = [&](int c) {
        const int st = c % NSTAGE;
        const uint32_t ab = sbase + st * STAGE_B;
        const uint32_t bb = ab + 16384;
        const int gk = c * 32;
#pragma unroll
        for (int q = 0; q < 4; q++) {
            int idx = tid + q * 256;                 // 0..1023
            int h = idx >> 9, rem = idx & 511;
            int r = rem >> 2, g = rem & 3;
            size_t go = (size_t)r * KDIM + gk + g * 8;
            uint32_t so = SWZ128((uint32_t)(r * 128 + h * 64 + g * 16));
            cp_async16(ab + so, (h ? Al : Ah) + go);
            cp_async16(bb + so, (h ? Bl : Bh) + go);
        }
        CP_COMMIT();
    };

    float acc[4][4][4];
#pragma unroll
    for (int i = 0; i < 4; i++)
#pragma unroll
        for (int j = 0; j < 4; j++)
#pragma unroll
            for (int q = 0; q < 4; q++) acc[i][j][q] = 0.f;

    issue_stage(0);
    issue_stage(1);

    constexpr int NCH = KDIM / 32;
    for (int c = 0; c < NCH; c++) {
        CP_WAIT1();                 // groups issued: 0..c+1 -> pending<=1 means group c done
        __syncthreads();            // cross-thread visibility + proves stage (c-1)%3 consumed
        if (c + 2 < NCH) issue_stage(c + 2);   // into stage (c-1)%3: race-free (header note)
        else CP_COMMIT();                       // empty group keeps counts monotone
        const uint32_t ab = sbase + (c % NSTAGE) * STAGE_B;
        const uint32_t bb = ab + 16384;
#pragma unroll
        for (int s = 0; s < 2; s++) {
            uint32_t bh[4][2], bl[4][2];
#pragma unroll
            for (int jp = 0; jp < 2; jp++) {
                uint32_t rB = wn * 32 + jp * 16 + laneRowB;
                uint32_t r4[4];
                ldsm_x4(r4, bb + SWZ128(rB * 128 + 0  + s * 32 + laneKBB));
                bh[jp * 2][0] = r4[0]; bh[jp * 2][1] = r4[1];
                bh[jp * 2 + 1][0] = r4[2]; bh[jp * 2 + 1][1] = r4[3];
                ldsm_x4(r4, bb + SWZ128(rB * 128 + 64 + s * 32 + laneKBB));
                bl[jp * 2][0] = r4[0]; bl[jp * 2][1] = r4[1];
                bl[jp * 2 + 1][0] = r4[2]; bl[jp * 2 + 1][1] = r4[3];
            }
#pragma unroll
            for (int i = 0; i < 4; i++) {
                uint32_t ah[4], al[4];
                uint32_t rA = wm * 64 + i * 16 + laneRowA;
                ldsm_x4(ah, ab + SWZ128(rA * 128 + 0  + s * 32 + laneKBA));
                ldsm_x4(al, ab + SWZ128(rA * 128 + 64 + s * 32 + laneKBA));
#pragma unroll
                for (int j = 0; j < 4; j++) {
                    mma16816(acc[i][j], ah, bh[j]);
                    mma16816(acc[i][j], ah, bl[j]);
                    mma16816(acc[i][j], al, bh[j]);
                }
            }
        }
        // no trailing barrier: next iteration's top barrier provides it
    }

    // ---------------- epilogue ----------------
    float2 bv[4];
#pragma unroll
    for (int j = 0; j < 4; j++) {
        int col = bn * 128 + wn * 32 + j * 8 + (lane & 3) * 2;
        bv[j] = *reinterpret_cast<const float2*>(bias + (size_t)e * NTOT + col);
    }

    if (PHASE1) {
#pragma unroll
        for (int i = 0; i < 4; i++) {
#pragma unroll
            for (int rr = 0; rr < 2; rr++) {
                int row = bm * 128 + wm * 64 + i * 16 + (lane >> 2) + rr * 8;
                size_t ro = ((size_t)e * CC + row) * NTOT;
#pragma unroll
                for (int j = 0; j < 4; j++) {
                    int col = bn * 128 + wn * 32 + j * 8 + (lane & 3) * 2;
                    float v0 = gelu_exact(acc[i][j][rr * 2 + 0] + bv[j].x);
                    float v1 = gelu_exact(acc[i][j][rr * 2 + 1] + bv[j].y);
                    __nv_bfloat16 h0 = __float2bfloat16(v0), h1 = __float2bfloat16(v1);
                    __nv_bfloat16 l0 = __float2bfloat16(v0 - __bfloat162float(h0));
                    __nv_bfloat16 l1 = __float2bfloat16(v1 - __bfloat162float(h1));
                    __nv_bfloat162 hh(h0, h1), ll(l0, l1);
                    *reinterpret_cast<uint32_t*>(g_h_hi + ro + col) = *(uint32_t*)&hh;
                    *reinterpret_cast<uint32_t*>(g_h_lo + ro + col) = *(uint32_t*)&ll;
                }
            }
        }
    } else {
#pragma unroll
        for (int i = 0; i < 4; i++) {
#pragma unroll
            for (int rr = 0; rr < 2; rr++) {
                int row = bm * 128 + wm * 64 + i * 16 + (lane >> 2) + rr * 8;
                int t = g_tok_of_slot[e * CC + row];
                if (t < 0) continue;
                float g = g_gate[t];
#pragma unroll
                for (int j = 0; j < 4; j++) {
                    int col = bn * 128 + wn * 32 + j * 8 + (lane & 3) * 2;
                    float2 v;
                    v.x = g * (acc[i][j][rr * 2 + 0] + bv[j].x);
                    v.y = g * (acc[i][j][rr * 2 + 1] + bv[j].y);
                    *reinterpret_cast<float2*>(outp + (size_t)t * DD + col) = v;
                }
            }
        }
    }
}

// ---------------- launch ----------------
extern "C" void kernel_launch(void* const* d_in, const int* in_sizes, int n_in,
                              void* d_out, int out_size) {
    (void)in_sizes; (void)n_in; (void)out_size;
    const float* x  = (const float*)d_in[0];
    const float* wr = (const float*)d_in[1];
    const float* br = (const float*)d_in[2];
    const float* w1 = (const float*)d_in[3];
    const float* b1 = (const float*)d_in[4];
    const float* w2 = (const float*)d_in[5];
    const float* b2 = (const float*)d_in[6];
    float* out = (float*)d_out;

    cudaFuncSetAttribute(moe_gemm_mma<DD, FF, true>,
                         cudaFuncAttributeMaxDynamicSharedMemorySize, GEMM_SMEM);
    cudaFuncSetAttribute(moe_gemm_mma<FF, DD, false>,
                         cudaFuncAttributeMaxDynamicSharedMemorySize, GEMM_SMEM);

    init_kernel<<<(TT * DD / 4) / 256, 256>>>((float4*)out);
    router_kernel<<<TT / 8, 256>>>(x, wr, br);
    assign_kernel<<<1, 1024>>>();
    dispatch_kernel<<<EE * CC, 256>>>(x);
    // W1 [E, D, F] -> g_w1t [E, F, D]
    wsplit_run<<<dim3(FF / 32, DD / 32, EE), dim3(32, 8)>>>(w1, DD, FF, 1);
    // W2 [E, F, D] -> g_w2t [E, D, F]
    wsplit_run<<<dim3(DD / 32, FF / 32, EE), dim3(32, 8)>>>(w2, FF, DD, 0);
    moe_gemm_mma<DD, FF, true ><<<dim3(FF / 128, CC / 128, EE), 256, GEMM_SMEM>>>(b1, nullptr);
    moe_gemm_mma<FF, DD, false><<<dim3(DD / 128, CC / 128, EE), 256, GEMM_SMEM>>>(b2, out);
}

// round 10
// speedup vs baseline: 1.9667x; 1.0124x over previous
#include <cuda_runtime.h>
#include <cuda_bf16.h>
#include <math.h>
#include <stdint.h>

// Problem dims (fixed by the reference)
#define TT 4096   // tokens = B*S
#define DD 1024   // model dim
#define FF 4096   // ffn dim
#define EE 8      // experts
#define CC 512    // capacity

// ---------------- scratch (device globals; no runtime allocation) ----------------
__device__ float g_gate[TT];
__device__ int   g_expert[TT];
__device__ int   g_tok_of_slot[EE * CC];

// __align__(16): accessed via uint2/uint4/cp.async 16B.
__device__ __align__(16) __nv_bfloat16 g_a_hi[EE * CC * DD];
__device__ __align__(16) __nv_bfloat16 g_a_lo[EE * CC * DD];
__device__ __align__(16) __nv_bfloat16 g_w1t_hi[(size_t)EE * FF * DD];  // W1^T [E, F(N), D(K)]
__device__ __align__(16) __nv_bfloat16 g_w1t_lo[(size_t)EE * FF * DD];
__device__ __align__(16) __nv_bfloat16 g_w2t_hi[(size_t)EE * DD * FF];  // W2^T [E, D(N), F(K)]
__device__ __align__(16) __nv_bfloat16 g_w2t_lo[(size_t)EE * DD * FF];
__device__ __align__(16) __nv_bfloat16 g_h_hi[(size_t)EE * CC * FF];    // hidden, hi/lo split
__device__ __align__(16) __nv_bfloat16 g_h_lo[(size_t)EE * CC * FF];

// ---------------- helpers (baseline sm_80+ features only) ----------------
__device__ __forceinline__ uint32_t smem_u32(const void* p) {
    uint32_t a;
    asm("{ .reg .u64 t; cvta.to.shared.u64 t, %1; cvt.u32.u64 %0, t; }" : "=r"(a) : "l"(p));
    return a;
}
__device__ __forceinline__ void cp_async16(uint32_t saddr, const void* gaddr) {
    asm volatile("cp.async.cg.shared.global [%0], [%1], 16;" :: "r"(saddr), "l"(gaddr) : "memory");
}
#define CP_COMMIT()  asm volatile("cp.async.commit_group;" ::: "memory")
#define CP_WAIT1()   asm volatile("cp.async.wait_group 1;" ::: "memory")

__device__ __forceinline__ void ldsm_x4(uint32_t* r, uint32_t addr) {
    asm volatile("ldmatrix.sync.aligned.m8n8.x4.shared.b16 {%0,%1,%2,%3}, [%4];"
                 : "=r"(r[0]), "=r"(r[1]), "=r"(r[2]), "=r"(r[3]) : "r"(addr));
}
__device__ __forceinline__ void mma16816(float* c, const uint32_t* a, const uint32_t* b) {
    asm volatile(
        "mma.sync.aligned.m16n8k16.row.col.f32.bf16.bf16.f32 "
        "{%0,%1,%2,%3}, {%4,%5,%6,%7}, {%8,%9}, {%0,%1,%2,%3};"
        : "+f"(c[0]), "+f"(c[1]), "+f"(c[2]), "+f"(c[3])
        : "r"(a[0]), "r"(a[1]), "r"(a[2]), "r"(a[3]), "r"(b[0]), "r"(b[1]));
}
#define SWZ128(o) ((o) ^ (((o) >> 3) & 0x70))

__device__ __forceinline__ float gelu_exact(float v) {
    return 0.5f * v * (1.0f + erff(v * 0.70710678118654752440f));
}

// ---------------- 1: fused init (zero out, slots=-1) + router ----------------
// grid 4096 x 256. All blocks zero their out chunk; blocks 0..511 also route
// 8 tokens each (one warp per token); first 16 blocks init tok_of_slot.
__global__ void init_router_kernel(float4* __restrict__ out4,
                                   const float* __restrict__ x,
                                   const float* __restrict__ wr,
                                   const float* __restrict__ br) {
    int i = blockIdx.x * 256 + threadIdx.x;
    out4[i] = make_float4(0.f, 0.f, 0.f, 0.f);
    if (i < EE * CC) g_tok_of_slot[i] = -1;

    int gw = (blockIdx.x * blockDim.x + threadIdx.x) >> 5;   // global warp = token
    int lane = threadIdx.x & 31;
    if (gw >= TT) return;
    const float* xt = x + (size_t)gw * DD;
    float acc[EE];
#pragma unroll
    for (int e = 0; e < EE; e++) acc[e] = 0.f;
    for (int d = lane; d < DD; d += 32) {
        float xv = xt[d];
        const float4* w4 = reinterpret_cast<const float4*>(wr + (size_t)d * EE);
        float4 wa = w4[0], wb = w4[1];
        acc[0] += xv * wa.x; acc[1] += xv * wa.y; acc[2] += xv * wa.z; acc[3] += xv * wa.w;
        acc[4] += xv * wb.x; acc[5] += xv * wb.y; acc[6] += xv * wb.z; acc[7] += xv * wb.w;
    }
#pragma unroll
    for (int e = 0; e < EE; e++)
#pragma unroll
        for (int o = 16; o > 0; o >>= 1) acc[e] += __shfl_xor_sync(0xffffffffu, acc[e], o);
    if (lane == 0) {
        float l[EE]; float best = -1e30f; int bi = 0;
#pragma unroll
        for (int e = 0; e < EE; e++) {
            l[e] = acc[e] + br[e];
            if (l[e] > best) { best = l[e]; bi = e; }
        }
        float s = 0.f;
#pragma unroll
        for (int e = 0; e < EE; e++) s += expf(l[e] - best);
        g_gate[gw] = 1.0f / s;
        g_expert[gw] = bi;
    }
}

// ---------------- 2: ordered capacity assignment (unchanged) ----------------
__global__ void assign_kernel() {
    __shared__ int s_warpcnt[EE][32], s_warpoff[EE][32], s_chunktot[EE], s_base[EE];
    int tid = threadIdx.x, lane = tid & 31, wid = tid >> 5;
    if (tid < EE) s_base[tid] = 0;
    for (int chunk = 0; chunk < TT; chunk += 1024) {
        __syncthreads();
        int t = chunk + tid;
        int e = g_expert[t];
        int inwarp = 0;
#pragma unroll
        for (int ee = 0; ee < EE; ee++) {
            unsigned m = __ballot_sync(0xffffffffu, e == ee);
            if (lane == 0) s_warpcnt[ee][wid] = __popc(m);
            if (e == ee) inwarp = __popc(m & ((1u << lane) - 1u));
        }
        __syncthreads();
        if (wid < EE) {
            int v = s_warpcnt[wid][lane], sc = v;
#pragma unroll
            for (int o = 1; o < 32; o <<= 1) {
                int n = __shfl_up_sync(0xffffffffu, sc, o);
                if (lane >= o) sc += n;
            }
            s_warpoff[wid][lane] = sc - v;
            if (lane == 31) s_chunktot[wid] = sc;
        }
        __syncthreads();
        int pos = s_base[e] + s_warpoff[e][wid] + inwarp + 1;  // 1-based (reference quirk)
        if (pos < CC) g_tok_of_slot[e * CC + pos] = t;
        else          g_gate[t] = 0.f;
        __syncthreads();
        if (tid < EE) s_base[tid] += s_chunktot[tid];
    }
}

// ---------------- 3: fused dispatch + wsplit(w1) + wsplit(w2) ----------------
// Block ranges: [0,4096) dispatch; [4096, 4096+32768) wsplit w1; rest wsplit w2.
#define DISP_BLKS (EE * CC)
#define W1_BLKS   ((FF / 32) * (DD / 32) * EE)
#define W2_BLKS   ((DD / 32) * (FF / 32) * EE)

__device__ __forceinline__ void wsplit_body(const float* __restrict__ Wp,
                                            __nv_bfloat16* __restrict__ hi,
                                            __nv_bfloat16* __restrict__ lo,
                                            int R, int Cn, int bx, int by, size_t base) {
    __shared__ float t[32][33];
    int tx = threadIdx.x & 31, ty = threadIdx.x >> 5;   // 32 x 8
    int c  = bx * 32 + tx;
    int r0 = by * 32 + ty;
#pragma unroll
    for (int i = 0; i < 4; i++)
        t[ty + i * 8][tx] = Wp[(size_t)(r0 + i * 8) * Cn + c];
    __syncthreads();
    int oc = by * 32 + tx;                              // k index (orig row)
#pragma unroll
    for (int i = 0; i < 4; i++) {
        int orr = bx * 32 + ty + i * 8;                 // n index (orig col)
        float v = t[tx][ty + i * 8];
        __nv_bfloat16 h = __float2bfloat16(v);
        float lf = v - __bfloat162float(h);
        hi[base + (size_t)orr * R + oc] = h;
        lo[base + (size_t)orr * R + oc] = __float2bfloat16(lf);
    }
}

__global__ void dispatch_wsplit_kernel(const float* __restrict__ x,
                                       const float* __restrict__ w1,
                                       const float* __restrict__ w2) {
    int b = blockIdx.x;
    if (b < DISP_BLKS) {
        // ---- dispatch: gate-scaled bf16 hi/lo scatter ----
        int slot = b;
        int t = g_tok_of_slot[slot];
        int i = threadIdx.x;
        uint2* dh = reinterpret_cast<uint2*>(g_a_hi + (size_t)slot * DD) + i;
        uint2* dl = reinterpret_cast<uint2*>(g_a_lo + (size_t)slot * DD) + i;
        if (t < 0) { *dh = make_uint2(0u, 0u); *dl = make_uint2(0u, 0u); return; }
        float g = g_gate[t];
        float4 v = reinterpret_cast<const float4*>(x)[(size_t)t * (DD / 4) + i];
        float f[4] = { v.x * g, v.y * g, v.z * g, v.w * g };
        __nv_bfloat16 hi[4], lo[4];
#pragma unroll
        for (int k = 0; k < 4; k++) {
            hi[k] = __float2bfloat16(f[k]);
            lo[k] = __float2bfloat16(f[k] - __bfloat162float(hi[k]));
        }
        __nv_bfloat162 h0(hi[0], hi[1]), h1(hi[2], hi[3]), l0(lo[0], lo[1]), l1(lo[2], lo[3]);
        *dh = make_uint2(*(uint32_t*)&h0, *(uint32_t*)&h1);
        *dl = make_uint2(*(uint32_t*)&l0, *(uint32_t*)&l1);
    } else if (b < DISP_BLKS + W1_BLKS) {
        // ---- wsplit w1: [E, D, F] f32 -> [E, F, D] bf16 hi/lo ----
        int idx = b - DISP_BLKS;
        int bx = idx % (FF / 32);
        int by = (idx / (FF / 32)) % (DD / 32);
        int e  = idx / ((FF / 32) * (DD / 32));
        wsplit_body(w1 + (size_t)e * DD * FF, g_w1t_hi, g_w1t_lo,
                    DD, FF, bx, by, (size_t)e * DD * FF);
    } else {
        // ---- wsplit w2: [E, F, D] f32 -> [E, D, F] bf16 hi/lo ----
        int idx = b - DISP_BLKS - W1_BLKS;
        int bx = idx % (DD / 32);
        int by = (idx / (DD / 32)) % (FF / 32);
        int e  = idx / ((DD / 32) * (FF / 32));
        wsplit_body(w2 + (size_t)e * FF * DD, g_w2t_hi, g_w2t_lo,
                    FF, DD, bx, by, (size_t)e * FF * DD);
    }
}

// ---------------- 4/5: grouped GEMM via mma.sync bf16 hi/lo split (3 MMAs) --------
// (byte-identical to round-9 champion: 128x128 tile, 8 warps 2x4, K-chunk 32,
//  NSTAGE=3 + launch_bounds(256,2) => 2 CTAs/SM, single barrier per chunk)
#define NSTAGE  3
#define STAGE_B 32768
#define GEMM_SMEM (NSTAGE * STAGE_B)   // 98304 B

template <int KDIM, int NTOT, bool PHASE1>
__global__ void __launch_bounds__(256, 2)
moe_gemm_mma(const float* __restrict__ bias, float* __restrict__ outp) {
    extern __shared__ __align__(1024) char smem[];
    const uint32_t sbase = smem_u32(smem);
    const int tid = threadIdx.x;
    const int lane = tid & 31, warp = tid >> 5;
    const int wm = warp & 1, wn = warp >> 1;            // warp at (64*wm, 32*wn)
    const int e = blockIdx.z, bm = blockIdx.y, bn = blockIdx.x;

    const __nv_bfloat16* Ah = (PHASE1 ? g_a_hi : g_h_hi) + ((size_t)e * CC + bm * 128) * KDIM;
    const __nv_bfloat16* Al = (PHASE1 ? g_a_lo : g_h_lo) + ((size_t)e * CC + bm * 128) * KDIM;
    const __nv_bfloat16* Bh = (PHASE1 ? g_w1t_hi : g_w2t_hi) + ((size_t)e * NTOT + bn * 128) * KDIM;
    const __nv_bfloat16* Bl = (PHASE1 ? g_w1t_lo : g_w2t_lo) + ((size_t)e * NTOT + bn * 128) * KDIM;

    const uint32_t laneRowA = (lane & 7) + ((lane >> 3) & 1) * 8;
    const uint32_t laneKBA  = ((lane >> 4) & 1) * 16;
    const uint32_t matB     = lane >> 3;
    const uint32_t laneRowB = (lane & 7) + (matB >> 1) * 8;
    const uint32_t laneKBB  = (matB & 1) * 16;

    auto issue_stage = [&](int c) {
        const int st = c % NSTAGE;
        const uint32_t ab = sbase + st * STAGE_B;
        const uint32_t bb = ab + 16384;
        const int gk = c * 32;
#pragma unroll
        for (int q = 0; q < 4; q++) {
            int idx = tid + q * 256;
            int h = idx >> 9, rem = idx & 511;
            int r = rem >> 2, g = rem & 3;
            size_t go = (size_t)r * KDIM + gk + g * 8;
            uint32_t so = SWZ128((uint32_t)(r * 128 + h * 64 + g * 16));
            cp_async16(ab + so, (h ? Al : Ah) + go);
            cp_async16(bb + so, (h ? Bl : Bh) + go);
        }
        CP_COMMIT();
    };

    float acc[4][4][4];
#pragma unroll
    for (int i = 0; i < 4; i++)
#pragma unroll
        for (int j = 0; j < 4; j++)
#pragma unroll
            for (int q = 0; q < 4; q++) acc[i][j][q] = 0.f;

    issue_stage(0);
    issue_stage(1);

    constexpr int NCH = KDIM / 32;
    for (int c = 0; c < NCH; c++) {
        CP_WAIT1();
        __syncthreads();
        if (c + 2 < NCH) issue_stage(c + 2);
        else CP_COMMIT();
        const uint32_t ab = sbase + (c % NSTAGE) * STAGE_B;
        const uint32_t bb = ab + 16384;
#pragma unroll
        for (int s = 0; s < 2; s++) {
            uint32_t bh[4][2], bl[4][2];
#pragma unroll
            for (int jp = 0; jp < 2; jp++) {
                uint32_t rB = wn * 32 + jp * 16 + laneRowB;
                uint32_t r4[4];
                ldsm_x4(r4, bb + SWZ128(rB * 128 + 0  + s * 32 + laneKBB));
                bh[jp * 2][0] = r4[0]; bh[jp * 2][1] = r4[1];
                bh[jp * 2 + 1][0] = r4[2]; bh[jp * 2 + 1][1] = r4[3];
                ldsm_x4(r4, bb + SWZ128(rB * 128 + 64 + s * 32 + laneKBB));
                bl[jp * 2][0] = r4[0]; bl[jp * 2][1] = r4[1];
                bl[jp * 2 + 1][0] = r4[2]; bl[jp * 2 + 1][1] = r4[3];
            }
#pragma unroll
            for (int i = 0; i < 4; i++) {
                uint32_t ah[4], al[4];
                uint32_t rA = wm * 64 + i * 16 + laneRowA;
                ldsm_x4(ah, ab + SWZ128(rA * 128 + 0  + s * 32 + laneKBA));
                ldsm_x4(al, ab + SWZ128(rA * 128 + 64 + s * 32 + laneKBA));
#pragma unroll
                for (int j = 0; j < 4; j++) {
                    mma16816(acc[i][j], ah, bh[j]);
                    mma16816(acc[i][j], ah, bl[j]);
                    mma16816(acc[i][j], al, bh[j]);
                }
            }
        }
    }

    // ---------------- epilogue ----------------
    float2 bv[4];
#pragma unroll
    for (int j = 0; j < 4; j++) {
        int col = bn * 128 + wn * 32 + j * 8 + (lane & 3) * 2;
        bv[j] = *reinterpret_cast<const float2*>(bias + (size_t)e * NTOT + col);
    }

    if (PHASE1) {
#pragma unroll
        for (int i = 0; i < 4; i++) {
#pragma unroll
            for (int rr = 0; rr < 2; rr++) {
                int row = bm * 128 + wm * 64 + i * 16 + (lane >> 2) + rr * 8;
                size_t ro = ((size_t)e * CC + row) * NTOT;
#pragma unroll
                for (int j = 0; j < 4; j++) {
                    int col = bn * 128 + wn * 32 + j * 8 + (lane & 3) * 2;
                    float v0 = gelu_exact(acc[i][j][rr * 2 + 0] + bv[j].x);
                    float v1 = gelu_exact(acc[i][j][rr * 2 + 1] + bv[j].y);
                    __nv_bfloat16 h0 = __float2bfloat16(v0), h1 = __float2bfloat16(v1);
                    __nv_bfloat16 l0 = __float2bfloat16(v0 - __bfloat162float(h0));
                    __nv_bfloat16 l1 = __float2bfloat16(v1 - __bfloat162float(h1));
                    __nv_bfloat162 hh(h0, h1), ll(l0, l1);
                    *reinterpret_cast<uint32_t*>(g_h_hi + ro + col) = *(uint32_t*)&hh;
                    *reinterpret_cast<uint32_t*>(g_h_lo + ro + col) = *(uint32_t*)&ll;
                }
            }
        }
    } else {
#pragma unroll
        for (int i = 0; i < 4; i++) {
#pragma unroll
            for (int rr = 0; rr < 2; rr++) {
                int row = bm * 128 + wm * 64 + i * 16 + (lane >> 2) + rr * 8;
                int t = g_tok_of_slot[e * CC + row];
                if (t < 0) continue;
                float g = g_gate[t];
#pragma unroll
                for (int j = 0; j < 4; j++) {
                    int col = bn * 128 + wn * 32 + j * 8 + (lane & 3) * 2;
                    float2 v;
                    v.x = g * (acc[i][j][rr * 2 + 0] + bv[j].x);
                    v.y = g * (acc[i][j][rr * 2 + 1] + bv[j].y);
                    *reinterpret_cast<float2*>(outp + (size_t)t * DD + col) = v;
                }
            }
        }
    }
}

// ---------------- launch (5 launches; GEMM1 is launch #4) ----------------
extern "C" void kernel_launch(void* const* d_in, const int* in_sizes, int n_in,
                              void* d_out, int out_size) {
    (void)in_sizes; (void)n_in; (void)out_size;
    const float* x  = (const float*)d_in[0];
    const float* wr = (const float*)d_in[1];
    const float* br = (const float*)d_in[2];
    const float* w1 = (const float*)d_in[3];
    const float* b1 = (const float*)d_in[4];
    const float* w2 = (const float*)d_in[5];
    const float* b2 = (const float*)d_in[6];
    float* out = (float*)d_out;

    cudaFuncSetAttribute(moe_gemm_mma<DD, FF, true>,
                         cudaFuncAttributeMaxDynamicSharedMemorySize, GEMM_SMEM);
    cudaFuncSetAttribute(moe_gemm_mma<FF, DD, false>,
                         cudaFuncAttributeMaxDynamicSharedMemorySize, GEMM_SMEM);

    init_router_kernel<<<(TT * DD / 4) / 256, 256>>>((float4*)out, x, wr, br);
    assign_kernel<<<1, 1024>>>();
    dispatch_wsplit_kernel<<<DISP_BLKS + W1_BLKS + W2_BLKS, 256>>>(x, w1, w2);
    moe_gemm_mma<DD, FF, true ><<<dim3(FF / 128, CC / 128, EE), 256, GEMM_SMEM>>>(b1, nullptr);
    moe_gemm_mma<FF, DD, false><<<dim3(DD / 128, CC / 128, EE), 256, GEMM_SMEM>>>(b2, out);
}

// round 11
// speedup vs baseline: 2.7567x; 1.4017x over previous
#include <cuda_runtime.h>
#include <cuda_fp16.h>
#include <math.h>
#include <stdint.h>

// Problem dims (fixed by the reference)
#define TT 4096   // tokens = B*S
#define DD 1024   // model dim
#define FF 4096   // ffn dim
#define EE 8      // experts
#define CC 512    // capacity

// ---------------- scratch (device globals; no runtime allocation) ----------------
__device__ float g_gate[TT];
__device__ int   g_expert[TT];
__device__ int   g_tok_of_slot[EE * CC];

// fp16 operands. A and h are SINGLE fp16 (quant ~2.8e-4 RMS); weights are hi/lo
// split fp16 (error ~2^-22, negligible). __align__(16) for vector/cp.async access.
__device__ __align__(16) __half g_a[EE * CC * DD];
__device__ __align__(16) __half g_w1t_hi[(size_t)EE * FF * DD];  // W1^T [E, F(N), D(K)]
__device__ __align__(16) __half g_w1t_lo[(size_t)EE * FF * DD];
__device__ __align__(16) __half g_w2t_hi[(size_t)EE * DD * FF];  // W2^T [E, D(N), F(K)]
__device__ __align__(16) __half g_w2t_lo[(size_t)EE * DD * FF];
__device__ __align__(16) __half g_h[(size_t)EE * CC * FF];       // hidden, single fp16

// ---------------- helpers (baseline sm_80+ features only) ----------------
__device__ __forceinline__ uint32_t smem_u32(const void* p) {
    uint32_t a;
    asm("{ .reg .u64 t; cvta.to.shared.u64 t, %1; cvt.u32.u64 %0, t; }" : "=r"(a) : "l"(p));
    return a;
}
__device__ __forceinline__ void cp_async16(uint32_t saddr, const void* gaddr) {
    asm volatile("cp.async.cg.shared.global [%0], [%1], 16;" :: "r"(saddr), "l"(gaddr) : "memory");
}
#define CP_COMMIT()  asm volatile("cp.async.commit_group;" ::: "memory")
#define CP_WAIT1()   asm volatile("cp.async.wait_group 1;" ::: "memory")

__device__ __forceinline__ void ldsm_x4(uint32_t* r, uint32_t addr) {
    asm volatile("ldmatrix.sync.aligned.m8n8.x4.shared.b16 {%0,%1,%2,%3}, [%4];"
                 : "=r"(r[0]), "=r"(r[1]), "=r"(r[2]), "=r"(r[3]) : "r"(addr));
}
__device__ __forceinline__ void mma16816(float* c, const uint32_t* a, const uint32_t* b) {
    asm volatile(
        "mma.sync.aligned.m16n8k16.row.col.f32.f16.f16.f32 "
        "{%0,%1,%2,%3}, {%4,%5,%6,%7}, {%8,%9}, {%0,%1,%2,%3};"
        : "+f"(c[0]), "+f"(c[1]), "+f"(c[2]), "+f"(c[3])
        : "r"(a[0]), "r"(a[1]), "r"(a[2]), "r"(a[3]), "r"(b[0]), "r"(b[1]));
}
#define SWZ128(o) ((o) ^ (((o) >> 3) & 0x70))

__device__ __forceinline__ float gelu_exact(float v) {
    return 0.5f * v * (1.0f + erff(v * 0.70710678118654752440f));
}
__device__ __forceinline__ uint32_t pack_h2(float a, float b) {
    __half2 h = __floats2half2_rn(a, b);
    return *reinterpret_cast<uint32_t*>(&h);
}

// ---------------- 1: fused init (zero out, slots=-1) + router ----------------
__global__ void init_router_kernel(float4* __restrict__ out4,
                                   const float* __restrict__ x,
                                   const float* __restrict__ wr,
                                   const float* __restrict__ br) {
    int i = blockIdx.x * 256 + threadIdx.x;
    out4[i] = make_float4(0.f, 0.f, 0.f, 0.f);
    if (i < EE * CC) g_tok_of_slot[i] = -1;

    int gw = (blockIdx.x * blockDim.x + threadIdx.x) >> 5;   // global warp = token
    int lane = threadIdx.x & 31;
    if (gw >= TT) return;
    const float* xt = x + (size_t)gw * DD;
    float acc[EE];
#pragma unroll
    for (int e = 0; e < EE; e++) acc[e] = 0.f;
    for (int d = lane; d < DD; d += 32) {
        float xv = xt[d];
        const float4* w4 = reinterpret_cast<const float4*>(wr + (size_t)d * EE);
        float4 wa = w4[0], wb = w4[1];
        acc[0] += xv * wa.x; acc[1] += xv * wa.y; acc[2] += xv * wa.z; acc[3] += xv * wa.w;
        acc[4] += xv * wb.x; acc[5] += xv * wb.y; acc[6] += xv * wb.z; acc[7] += xv * wb.w;
    }
#pragma unroll
    for (int e = 0; e < EE; e++)
#pragma unroll
        for (int o = 16; o > 0; o >>= 1) acc[e] += __shfl_xor_sync(0xffffffffu, acc[e], o);
    if (lane == 0) {
        float l[EE]; float best = -1e30f; int bi = 0;
#pragma unroll
        for (int e = 0; e < EE; e++) {
            l[e] = acc[e] + br[e];
            if (l[e] > best) { best = l[e]; bi = e; }
        }
        float s = 0.f;
#pragma unroll
        for (int e = 0; e < EE; e++) s += expf(l[e] - best);
        g_gate[gw] = 1.0f / s;
        g_expert[gw] = bi;
    }
}

// ---------------- 2: ordered capacity assignment (unchanged) ----------------
__global__ void assign_kernel() {
    __shared__ int s_warpcnt[EE][32], s_warpoff[EE][32], s_chunktot[EE], s_base[EE];
    int tid = threadIdx.x, lane = tid & 31, wid = tid >> 5;
    if (tid < EE) s_base[tid] = 0;
    for (int chunk = 0; chunk < TT; chunk += 1024) {
        __syncthreads();
        int t = chunk + tid;
        int e = g_expert[t];
        int inwarp = 0;
#pragma unroll
        for (int ee = 0; ee < EE; ee++) {
            unsigned m = __ballot_sync(0xffffffffu, e == ee);
            if (lane == 0) s_warpcnt[ee][wid] = __popc(m);
            if (e == ee) inwarp = __popc(m & ((1u << lane) - 1u));
        }
        __syncthreads();
        if (wid < EE) {
            int v = s_warpcnt[wid][lane], sc = v;
#pragma unroll
            for (int o = 1; o < 32; o <<= 1) {
                int n = __shfl_up_sync(0xffffffffu, sc, o);
                if (lane >= o) sc += n;
            }
            s_warpoff[wid][lane] = sc - v;
            if (lane == 31) s_chunktot[wid] = sc;
        }
        __syncthreads();
        int pos = s_base[e] + s_warpoff[e][wid] + inwarp + 1;  // 1-based (reference quirk)
        if (pos < CC) g_tok_of_slot[e * CC + pos] = t;
        else          g_gate[t] = 0.f;
        __syncthreads();
        if (tid < EE) s_base[tid] += s_chunktot[tid];
    }
}

// ---------------- 3: fused dispatch + wsplit(w1) + wsplit(w2) ----------------
#define DISP_BLKS (EE * CC)
#define W1_BLKS   ((FF / 32) * (DD / 32) * EE)
#define W2_BLKS   ((DD / 32) * (FF / 32) * EE)

__device__ __forceinline__ void wsplit_body(const float* __restrict__ Wp,
                                            __half* __restrict__ hi,
                                            __half* __restrict__ lo,
                                            int R, int Cn, int bx, int by, size_t base) {
    __shared__ float t[32][33];
    int tx = threadIdx.x & 31, ty = threadIdx.x >> 5;   // 32 x 8
    int c  = bx * 32 + tx;
    int r0 = by * 32 + ty;
#pragma unroll
    for (int i = 0; i < 4; i++)
        t[ty + i * 8][tx] = Wp[(size_t)(r0 + i * 8) * Cn + c];
    __syncthreads();
    int oc = by * 32 + tx;                              // k index (orig row)
#pragma unroll
    for (int i = 0; i < 4; i++) {
        int orr = bx * 32 + ty + i * 8;                 // n index (orig col)
        float v = t[tx][ty + i * 8];
        __half h = __float2half_rn(v);
        float lf = v - __half2float(h);
        hi[base + (size_t)orr * R + oc] = h;
        lo[base + (size_t)orr * R + oc] = __float2half_rn(lf);
    }
}

__global__ void dispatch_wsplit_kernel(const float* __restrict__ x,
                                       const float* __restrict__ w1,
                                       const float* __restrict__ w2) {
    int b = blockIdx.x;
    if (b < DISP_BLKS) {
        // ---- dispatch: gate-scaled single-fp16 scatter ----
        int slot = b;
        int t = g_tok_of_slot[slot];
        int i = threadIdx.x;                             // 256 threads, 4 elems each
        uint2* da = reinterpret_cast<uint2*>(g_a + (size_t)slot * DD) + i;
        if (t < 0) { *da = make_uint2(0u, 0u); return; }
        float g = g_gate[t];
        float4 v = reinterpret_cast<const float4*>(x)[(size_t)t * (DD / 4) + i];
        *da = make_uint2(pack_h2(v.x * g, v.y * g), pack_h2(v.z * g, v.w * g));
    } else if (b < DISP_BLKS + W1_BLKS) {
        int idx = b - DISP_BLKS;
        int bx = idx % (FF / 32);
        int by = (idx / (FF / 32)) % (DD / 32);
        int e  = idx / ((FF / 32) * (DD / 32));
        wsplit_body(w1 + (size_t)e * DD * FF, g_w1t_hi, g_w1t_lo,
                    DD, FF, bx, by, (size_t)e * DD * FF);
    } else {
        int idx = b - DISP_BLKS - W1_BLKS;
        int bx = idx % (DD / 32);
        int by = (idx / (DD / 32)) % (FF / 32);
        int e  = idx / ((DD / 32) * (FF / 32));
        wsplit_body(w2 + (size_t)e * FF * DD, g_w2t_hi, g_w2t_lo,
                    FF, DD, bx, by, (size_t)e * FF * DD);
    }
}

// ---------------- 4/5: grouped GEMM, fp16, 2 MMAs (A x B_hi + A x B_lo) --------
// CTA tile 128(M)x128(N), K-chunk 64. 8 warps in 2(M)x4(N); warp tile 64x32.
// Stage = A(16KB) + Bh(16KB) + Bl(16KB) = 48KB; NSTAGE=2 (96KB) -> 2 CTAs/SM.
// 2-stage schedule: wait(c) -> sync -> compute(c) -> sync -> issue(c+2 into c%2).
#define NSTAGE  2
#define STAGE_B 49152
#define TILE16K 16384
#define GEMM_SMEM (NSTAGE * STAGE_B)   // 98304 B

template <int KDIM, int NTOT, bool PHASE1>
__global__ void __launch_bounds__(256, 2)
moe_gemm_mma(const float* __restrict__ bias, float* __restrict__ outp) {
    extern __shared__ __align__(1024) char smem[];
    const uint32_t sbase = smem_u32(smem);
    const int tid = threadIdx.x;
    const int lane = tid & 31, warp = tid >> 5;
    const int wm = warp & 1, wn = warp >> 1;            // warp at (64*wm, 32*wn)
    const int e = blockIdx.z, bm = blockIdx.y, bn = blockIdx.x;

    const __half* A  = (PHASE1 ? g_a : g_h) + ((size_t)e * CC + bm * 128) * KDIM;
    const __half* Bh = (PHASE1 ? g_w1t_hi : g_w2t_hi) + ((size_t)e * NTOT + bn * 128) * KDIM;
    const __half* Bl = (PHASE1 ? g_w1t_lo : g_w2t_lo) + ((size_t)e * NTOT + bn * 128) * KDIM;

    // ldmatrix lane addressing (constant per thread)
    const uint32_t laneRowA = (lane & 7) + ((lane >> 3) & 1) * 8;   // + i*16 + wm*64
    const uint32_t laneKBA  = ((lane >> 4) & 1) * 16;               // k-byte block
    const uint32_t matB     = lane >> 3;
    const uint32_t laneRowB = (lane & 7) + (matB >> 1) * 8;         // + jp*16 + wn*32
    const uint32_t laneKBB  = (matB & 1) * 16;

    // Stage layout: [A 16KB | Bh 16KB | Bl 16KB], rows of 128B (64 fp16 k-values), SW128.
    auto issue_stage = [&](int c) {
        const uint32_t st = sbase + (c % NSTAGE) * STAGE_B;
        const int gk = c * 64;
#pragma unroll
        for (int q = 0; q < 4; q++) {
            int idx = tid + q * 256;                 // 0..1023
            int r = idx >> 3, j = idx & 7;
            size_t go = (size_t)r * KDIM + gk + j * 8;
            uint32_t so = SWZ128((uint32_t)(r * 128 + j * 16));
            cp_async16(st + 0 * TILE16K + so, A  + go);
            cp_async16(st + 1 * TILE16K + so, Bh + go);
            cp_async16(st + 2 * TILE16K + so, Bl + go);
        }
        CP_COMMIT();
    };

    float acc[4][4][4];
#pragma unroll
    for (int i = 0; i < 4; i++)
#pragma unroll
        for (int j = 0; j < 4; j++)
#pragma unroll
            for (int q = 0; q < 4; q++) acc[i][j][q] = 0.f;

    issue_stage(0);
    issue_stage(1);

    constexpr int NCH = KDIM / 64;
    for (int c = 0; c < NCH; c++) {
        CP_WAIT1();                 // groups 0..c+1 issued; pending<=1 => group c done
        __syncthreads();
        const uint32_t ab  = sbase + (c % NSTAGE) * STAGE_B;
        const uint32_t bbh = ab + 1 * TILE16K;
        const uint32_t bbl = ab + 2 * TILE16K;
#pragma unroll
        for (int s = 0; s < 4; s++) {               // 4 x k16 within the 64-k chunk
            uint32_t bh[4][2], bl[4][2];
#pragma unroll
            for (int jp = 0; jp < 2; jp++) {
                uint32_t rB = wn * 32 + jp * 16 + laneRowB;
                uint32_t r4[4];
                ldsm_x4(r4, bbh + SWZ128(rB * 128 + s * 32 + laneKBB));
                bh[jp * 2][0] = r4[0]; bh[jp * 2][1] = r4[1];
                bh[jp * 2 + 1][0] = r4[2]; bh[jp * 2 + 1][1] = r4[3];
                ldsm_x4(r4, bbl + SWZ128(rB * 128 + s * 32 + laneKBB));
                bl[jp * 2][0] = r4[0]; bl[jp * 2][1] = r4[1];
                bl[jp * 2 + 1][0] = r4[2]; bl[jp * 2 + 1][1] = r4[3];
            }
#pragma unroll
            for (int i = 0; i < 4; i++) {
                uint32_t ah[4];
                uint32_t rA = wm * 64 + i * 16 + laneRowA;
                ldsm_x4(ah, ab + SWZ128(rA * 128 + s * 32 + laneKBA));
#pragma unroll
                for (int j = 0; j < 4; j++) {
                    mma16816(acc[i][j], ah, bh[j]);
                    mma16816(acc[i][j], ah, bl[j]);
                }
            }
        }
        __syncthreads();            // all warps done reading stage c%2 before refill
        if (c + 2 < NCH) issue_stage(c + 2);
        else CP_COMMIT();           // empty group keeps counts monotone
    }

    // ---------------- epilogue ----------------
    float2 bv[4];
#pragma unroll
    for (int j = 0; j < 4; j++) {
        int col = bn * 128 + wn * 32 + j * 8 + (lane & 3) * 2;
        bv[j] = *reinterpret_cast<const float2*>(bias + (size_t)e * NTOT + col);
    }

    if (PHASE1) {
#pragma unroll
        for (int i = 0; i < 4; i++) {
#pragma unroll
            for (int rr = 0; rr < 2; rr++) {
                int row = bm * 128 + wm * 64 + i * 16 + (lane >> 2) + rr * 8;
                size_t ro = ((size_t)e * CC + row) * NTOT;
#pragma unroll
                for (int j = 0; j < 4; j++) {
                    int col = bn * 128 + wn * 32 + j * 8 + (lane & 3) * 2;
                    float v0 = gelu_exact(acc[i][j][rr * 2 + 0] + bv[j].x);
                    float v1 = gelu_exact(acc[i][j][rr * 2 + 1] + bv[j].y);
                    *reinterpret_cast<uint32_t*>(g_h + ro + col) = pack_h2(v0, v1);
                }
            }
        }
    } else {
#pragma unroll
        for (int i = 0; i < 4; i++) {
#pragma unroll
            for (int rr = 0; rr < 2; rr++) {
                int row = bm * 128 + wm * 64 + i * 16 + (lane >> 2) + rr * 8;
                int t = g_tok_of_slot[e * CC + row];
                if (t < 0) continue;
                float g = g_gate[t];
#pragma unroll
                for (int j = 0; j < 4; j++) {
                    int col = bn * 128 + wn * 32 + j * 8 + (lane & 3) * 2;
                    float2 v;
                    v.x = g * (acc[i][j][rr * 2 + 0] + bv[j].x);
                    v.y = g * (acc[i][j][rr * 2 + 1] + bv[j].y);
                    *reinterpret_cast<float2*>(outp + (size_t)t * DD + col) = v;
                }
            }
        }
    }
}

// ---------------- launch (5 launches; GEMM1 is launch #4) ----------------
extern "C" void kernel_launch(void* const* d_in, const int* in_sizes, int n_in,
                              void* d_out, int out_size) {
    (void)in_sizes; (void)n_in; (void)out_size;
    const float* x  = (const float*)d_in[0];
    const float* wr = (const float*)d_in[1];
    const float* br = (const float*)d_in[2];
    const float* w1 = (const float*)d_in[3];
    const float* b1 = (const float*)d_in[4];
    const float* w2 = (const float*)d_in[5];
    const float* b2 = (const float*)d_in[6];
    float* out = (float*)d_out;

    cudaFuncSetAttribute(moe_gemm_mma<DD, FF, true>,
                         cudaFuncAttributeMaxDynamicSharedMemorySize, GEMM_SMEM);
    cudaFuncSetAttribute(moe_gemm_mma<FF, DD, false>,
                         cudaFuncAttributeMaxDynamicSharedMemorySize, GEMM_SMEM);

    init_router_kernel<<<(TT * DD / 4) / 256, 256>>>((float4*)out, x, wr, br);
    assign_kernel<<<1, 1024>>>();
    dispatch_wsplit_kernel<<<DISP_BLKS + W1_BLKS + W2_BLKS, 256>>>(x, w1, w2);
    moe_gemm_mma<DD, FF, true ><<<dim3(FF / 128, CC / 128, EE), 256, GEMM_SMEM>>>(b1, nullptr);
    moe_gemm_mma<FF, DD, false><<<dim3(DD / 128, CC / 128, EE), 256, GEMM_SMEM>>>(b2, out);
}

// round 13
// speedup vs baseline: 4.1961x; 1.5221x over previous
#include <cuda_runtime.h>
#include <cuda_fp16.h>
#include <math.h>
#include <stdint.h>

// Problem dims (fixed by the reference)
#define TT 4096   // tokens = B*S
#define DD 1024   // model dim
#define FF 4096   // ffn dim
#define EE 8      // experts
#define CC 512    // capacity

// ---------------- scratch (device globals; no runtime allocation) ----------------
__device__ float g_gate[TT];
__device__ int   g_expert[TT];
__device__ int   g_tok_of_slot[EE * CC];

// Plain fp16 operands everywhere (quant ~2.1e-4 RMS per tensor; 4 sources
// -> ~4.2e-4 total, 2.4x margin under the 1e-3 gate).
__device__ __align__(16) __half g_a[EE * CC * DD];
__device__ __align__(16) __half g_w1t[(size_t)EE * FF * DD];  // W1^T [E, F(N), D(K)]
__device__ __align__(16) __half g_w2t[(size_t)EE * DD * FF];  // W2^T [E, D(N), F(K)]
__device__ __align__(16) __half g_h[(size_t)EE * CC * FF];    // hidden

// ---------------- helpers (baseline sm_80+ features only) ----------------
__device__ __forceinline__ uint32_t smem_u32(const void* p) {
    uint32_t a;
    asm("{ .reg .u64 t; cvta.to.shared.u64 t, %1; cvt.u32.u64 %0, t; }" : "=r"(a) : "l"(p));
    return a;
}
__device__ __forceinline__ void cp_async16(uint32_t saddr, const void* gaddr) {
    asm volatile("cp.async.cg.shared.global [%0], [%1], 16;" :: "r"(saddr), "l"(gaddr) : "memory");
}
#define CP_COMMIT()  asm volatile("cp.async.commit_group;" ::: "memory")
#define CP_WAIT1()   asm volatile("cp.async.wait_group 1;" ::: "memory")

__device__ __forceinline__ void ldsm_x4(uint32_t* r, uint32_t addr) {
    asm volatile("ldmatrix.sync.aligned.m8n8.x4.shared.b16 {%0,%1,%2,%3}, [%4];"
                 : "=r"(r[0]), "=r"(r[1]), "=r"(r[2]), "=r"(r[3]) : "r"(addr));
}
__device__ __forceinline__ void mma16816(float* c, const uint32_t* a, const uint32_t* b) {
    asm volatile(
        "mma.sync.aligned.m16n8k16.row.col.f32.f16.f16.f32 "
        "{%0,%1,%2,%3}, {%4,%5,%6,%7}, {%8,%9}, {%0,%1,%2,%3};"
        : "+f"(c[0]), "+f"(c[1]), "+f"(c[2]), "+f"(c[3])
        : "r"(a[0]), "r"(a[1]), "r"(a[2]), "r"(a[3]), "r"(b[0]), "r"(b[1]));
}
#define SWZ128(o) ((o) ^ (((o) >> 3) & 0x70))

__device__ __forceinline__ float gelu_exact(float v) {
    return 0.5f * v * (1.0f + erff(v * 0.70710678118654752440f));
}
__device__ __forceinline__ uint32_t pack_h2(float a, float b) {
    __half2 h = __floats2half2_rn(a, b);
    return *reinterpret_cast<uint32_t*>(&h);
}

// ---------------- 1: fused init (zero out, slots=-1) + router ----------------
__global__ void init_router_kernel(float4* __restrict__ out4,
                                   const float* __restrict__ x,
                                   const float* __restrict__ wr,
                                   const float* __restrict__ br) {
    int i = blockIdx.x * 256 + threadIdx.x;
    out4[i] = make_float4(0.f, 0.f, 0.f, 0.f);
    if (i < EE * CC) g_tok_of_slot[i] = -1;

    int gw = (blockIdx.x * blockDim.x + threadIdx.x) >> 5;   // global warp = token
    int lane = threadIdx.x & 31;
    if (gw >= TT) return;
    const float* xt = x + (size_t)gw * DD;
    float acc[EE];
#pragma unroll
    for (int e = 0; e < EE; e++) acc[e] = 0.f;
    for (int d = lane; d < DD; d += 32) {
        float xv = xt[d];
        const float4* w4 = reinterpret_cast<const float4*>(wr + (size_t)d * EE);
        float4 wa = w4[0], wb = w4[1];
        acc[0] += xv * wa.x; acc[1] += xv * wa.y; acc[2] += xv * wa.z; acc[3] += xv * wa.w;
        acc[4] += xv * wb.x; acc[5] += xv * wb.y; acc[6] += xv * wb.z; acc[7] += xv * wb.w;
    }
#pragma unroll
    for (int e = 0; e < EE; e++)
#pragma unroll
        for (int o = 16; o > 0; o >>= 1) acc[e] += __shfl_xor_sync(0xffffffffu, acc[e], o);
    if (lane == 0) {
        float l[EE]; float best = -1e30f; int bi = 0;
#pragma unroll
        for (int e = 0; e < EE; e++) {
            l[e] = acc[e] + br[e];
            if (l[e] > best) { best = l[e]; bi = e; }
        }
        float s = 0.f;
#pragma unroll
        for (int e = 0; e < EE; e++) s += expf(l[e] - best);
        g_gate[gw] = 1.0f / s;
        g_expert[gw] = bi;
    }
}

// ---------------- 2: ordered capacity assignment (unchanged) ----------------
__global__ void assign_kernel() {
    __shared__ int s_warpcnt[EE][32], s_warpoff[EE][32], s_chunktot[EE], s_base[EE];
    int tid = threadIdx.x, lane = tid & 31, wid = tid >> 5;
    if (tid < EE) s_base[tid] = 0;
    for (int chunk = 0; chunk < TT; chunk += 1024) {
        __syncthreads();
        int t = chunk + tid;
        int e = g_expert[t];
        int inwarp = 0;
#pragma unroll
        for (int ee = 0; ee < EE; ee++) {
            unsigned m = __ballot_sync(0xffffffffu, e == ee);
            if (lane == 0) s_warpcnt[ee][wid] = __popc(m);
            if (e == ee) inwarp = __popc(m & ((1u << lane) - 1u));
        }
        __syncthreads();
        if (wid < EE) {
            int v = s_warpcnt[wid][lane], sc = v;
#pragma unroll
            for (int o = 1; o < 32; o <<= 1) {
                int n = __shfl_up_sync(0xffffffffu, sc, o);
                if (lane >= o) sc += n;
            }
            s_warpoff[wid][lane] = sc - v;
            if (lane == 31) s_chunktot[wid] = sc;
        }
        __syncthreads();
        int pos = s_base[e] + s_warpoff[e][wid] + inwarp + 1;  // 1-based (reference quirk)
        if (pos < CC) g_tok_of_slot[e * CC + pos] = t;
        else          g_gate[t] = 0.f;
        __syncthreads();
        if (tid < EE) s_base[tid] += s_chunktot[tid];
    }
}

// ---------------- 3: fused dispatch + wsplit(w1) + wsplit(w2) ----------------
#define DISP_BLKS (EE * CC)
#define W1_BLKS   ((FF / 32) * (DD / 32) * EE)
#define W2_BLKS   ((DD / 32) * (FF / 32) * EE)

__device__ __forceinline__ void wsplit_body(const float* __restrict__ Wp,
                                            __half* __restrict__ Wt,
                                            int R, int Cn, int bx, int by, size_t base) {
    __shared__ float t[32][33];
    int tx = threadIdx.x & 31, ty = threadIdx.x >> 5;   // 32 x 8
    int c  = bx * 32 + tx;
    int r0 = by * 32 + ty;
#pragma unroll
    for (int i = 0; i < 4; i++)
        t[ty + i * 8][tx] = Wp[(size_t)(r0 + i * 8) * Cn + c];
    __syncthreads();
    int oc = by * 32 + tx;                              // k index (orig row)
#pragma unroll
    for (int i = 0; i < 4; i++) {
        int orr = bx * 32 + ty + i * 8;                 // n index (orig col)
        Wt[base + (size_t)orr * R + oc] = __float2half_rn(t[tx][ty + i * 8]);
    }
}

__global__ void dispatch_wsplit_kernel(const float* __restrict__ x,
                                       const float* __restrict__ w1,
                                       const float* __restrict__ w2) {
    int b = blockIdx.x;
    if (b < DISP_BLKS) {
        int slot = b;
        int t = g_tok_of_slot[slot];
        int i = threadIdx.x;                             // 256 threads, 4 elems each
        uint2* da = reinterpret_cast<uint2*>(g_a + (size_t)slot * DD) + i;
        if (t < 0) { *da = make_uint2(0u, 0u); return; }
        float g = g_gate[t];
        float4 v = reinterpret_cast<const float4*>(x)[(size_t)t * (DD / 4) + i];
        *da = make_uint2(pack_h2(v.x * g, v.y * g), pack_h2(v.z * g, v.w * g));
    } else if (b < DISP_BLKS + W1_BLKS) {
        int idx = b - DISP_BLKS;
        int bx = idx % (FF / 32);
        int by = (idx / (FF / 32)) % (DD / 32);
        int e  = idx / ((FF / 32) * (DD / 32));
        wsplit_body(w1 + (size_t)e * DD * FF, g_w1t, DD, FF, bx, by, (size_t)e * DD * FF);
    } else {
        int idx = b - DISP_BLKS - W1_BLKS;
        int bx = idx % (DD / 32);
        int by = (idx / (DD / 32)) % (FF / 32);
        int e  = idx / ((DD / 32) * (FF / 32));
        wsplit_body(w2 + (size_t)e * FF * DD, g_w2t, FF, DD, bx, by, (size_t)e * FF * DD);
    }
}

// ---------------- 4/5: grouped GEMM, plain fp16, 1 MMA ----------------
// CTA tile 128(M)x128(N), K-chunk 64. 8 warps in 2(M)x4(N); warp tile 64x32.
// Stage = A(16KB) + B(16KB) = 32KB; NSTAGE=3 (96KB) -> 2 CTAs/SM.
// Round-9-proven schedule: wait(c) -> sync -> issue(c+2 into stage (c-1)%3) -> compute.
#define NSTAGE  3
#define STAGE_B 32768
#define TILE16K 16384
#define GEMM_SMEM (NSTAGE * STAGE_B)   // 98304 B

template <int KDIM, int NTOT, bool PHASE1>
__global__ void __launch_bounds__(256, 2)
moe_gemm_mma(const float* __restrict__ bias, float* __restrict__ outp) {
    extern __shared__ __align__(1024) char smem[];
    const uint32_t sbase = smem_u32(smem);
    const int tid = threadIdx.x;
    const int lane = tid & 31, warp = tid >> 5;
    const int wm = warp & 1, wn = warp >> 1;            // warp at (64*wm, 32*wn)
    const int e = blockIdx.z, bm = blockIdx.y, bn = blockIdx.x;

    const __half* A = (PHASE1 ? g_a : g_h) + ((size_t)e * CC + bm * 128) * KDIM;
    const __half* B = (PHASE1 ? g_w1t : g_w2t) + ((size_t)e * NTOT + bn * 128) * KDIM;

    // ldmatrix lane addressing (constant per thread)
    const uint32_t laneRowA = (lane & 7) + ((lane >> 3) & 1) * 8;   // + i*16 + wm*64
    const uint32_t laneKBA  = ((lane >> 4) & 1) * 16;               // k-byte block
    const uint32_t matB     = lane >> 3;
    const uint32_t laneRowB = (lane & 7) + (matB >> 1) * 8;         // + jp*16 + wn*32
    const uint32_t laneKBB  = (matB & 1) * 16;

    // Stage layout: [A 16KB | B 16KB], rows of 128B (64 fp16 k-values), SW128.
    auto issue_stage = [&](int c) {
        const uint32_t st = sbase + (c % NSTAGE) * STAGE_B;
        const int gk = c * 64;
#pragma unroll
        for (int q = 0; q < 4; q++) {
            int idx = tid + q * 256;                 // 0..1023
            int r = idx >> 3, j = idx & 7;
            size_t go = (size_t)r * KDIM + gk + j * 8;
            uint32_t so = SWZ128((uint32_t)(r * 128 + j * 16));
            cp_async16(st + 0 * TILE16K + so, A + go);
            cp_async16(st + 1 * TILE16K + so, B + go);
        }
        CP_COMMIT();
    };

    float acc[4][4][4];
#pragma unroll
    for (int i = 0; i < 4; i++)
#pragma unroll
        for (int j = 0; j < 4; j++)
#pragma unroll
            for (int q = 0; q < 4; q++) acc[i][j][q] = 0.f;

    issue_stage(0);
    issue_stage(1);

    constexpr int NCH = KDIM / 64;
    for (int c = 0; c < NCH; c++) {
        CP_WAIT1();                 // groups 0..c+1 issued; pending<=1 => group c done
        __syncthreads();            // visibility + proves stage (c-1)%3 fully consumed
        if (c + 2 < NCH) issue_stage(c + 2);   // into stage (c-1)%3: race-free
        else CP_COMMIT();                       // empty group keeps counts monotone
        const uint32_t ab = sbase + (c % NSTAGE) * STAGE_B;
        const uint32_t bb = ab + TILE16K;
#pragma unroll
        for (int s = 0; s < 4; s++) {               // 4 x k16 within the 64-k chunk
            uint32_t bf[4][2];
#pragma unroll
            for (int jp = 0; jp < 2; jp++) {
                uint32_t rB = wn * 32 + jp * 16 + laneRowB;
                uint32_t r4[4];
                ldsm_x4(r4, bb + SWZ128(rB * 128 + s * 32 + laneKBB));
                bf[jp * 2][0] = r4[0]; bf[jp * 2][1] = r4[1];
                bf[jp * 2 + 1][0] = r4[2]; bf[jp * 2 + 1][1] = r4[3];
            }
#pragma unroll
            for (int i = 0; i < 4; i++) {
                uint32_t ah[4];
                uint32_t rA = wm * 64 + i * 16 + laneRowA;
                ldsm_x4(ah, ab + SWZ128(rA * 128 + s * 32 + laneKBA));
#pragma unroll
                for (int j = 0; j < 4; j++)
                    mma16816(acc[i][j], ah, bf[j]);
            }
        }
        // no trailing barrier: next iteration's top barrier provides it
    }

    // ---------------- epilogue ----------------
    float2 bv[4];
#pragma unroll
    for (int j = 0; j < 4; j++) {
        int col = bn * 128 + wn * 32 + j * 8 + (lane & 3) * 2;
        bv[j] = *reinterpret_cast<const float2*>(bias + (size_t)e * NTOT + col);
    }

    if (PHASE1) {
#pragma unroll
        for (int i = 0; i < 4; i++) {
#pragma unroll
            for (int rr = 0; rr < 2; rr++) {
                int row = bm * 128 + wm * 64 + i * 16 + (lane >> 2) + rr * 8;
                size_t ro = ((size_t)e * CC + row) * NTOT;
#pragma unroll
                for (int j = 0; j < 4; j++) {
                    int col = bn * 128 + wn * 32 + j * 8 + (lane & 3) * 2;
                    float v0 = gelu_exact(acc[i][j][rr * 2 + 0] + bv[j].x);
                    float v1 = gelu_exact(acc[i][j][rr * 2 + 1] + bv[j].y);
                    *reinterpret_cast<uint32_t*>(g_h + ro + col) = pack_h2(v0, v1);
                }
            }
        }
    } else {
#pragma unroll
        for (int i = 0; i < 4; i++) {
#pragma unroll
            for (int rr = 0; rr < 2; rr++) {
                int row = bm * 128 + wm * 64 + i * 16 + (lane >> 2) + rr * 8;
                int t = g_tok_of_slot[e * CC + row];
                if (t < 0) continue;
                float g = g_gate[t];
#pragma unroll
                for (int j = 0; j < 4; j++) {
                    int col = bn * 128 + wn * 32 + j * 8 + (lane & 3) * 2;
                    float2 v;
                    v.x = g * (acc[i][j][rr * 2 + 0] + bv[j].x);
                    v.y = g * (acc[i][j][rr * 2 + 1] + bv[j].y);
                    *reinterpret_cast<float2*>(outp + (size_t)t * DD + col) = v;
                }
            }
        }
    }
}

// ---------------- launch (5 launches; GEMM1 is launch #4) ----------------
extern "C" void kernel_launch(void* const* d_in, const int* in_sizes, int n_in,
                              void* d_out, int out_size) {
    (void)in_sizes; (void)n_in; (void)out_size;
    const float* x  = (const float*)d_in[0];
    const float* wr = (const float*)d_in[1];
    const float* br = (const float*)d_in[2];
    const float* w1 = (const float*)d_in[3];
    const float* b1 = (const float*)d_in[4];
    const float* w2 = (const float*)d_in[5];
    const float* b2 = (const float*)d_in[6];
    float* out = (float*)d_out;

    cudaFuncSetAttribute(moe_gemm_mma<DD, FF, true>,
                         cudaFuncAttributeMaxDynamicSharedMemorySize, GEMM_SMEM);
    cudaFuncSetAttribute(moe_gemm_mma<FF, DD, false>,
                         cudaFuncAttributeMaxDynamicSharedMemorySize, GEMM_SMEM);

    init_router_kernel<<<(TT * DD / 4) / 256, 256>>>((float4*)out, x, wr, br);
    assign_kernel<<<1, 1024>>>();
    dispatch_wsplit_kernel<<<DISP_BLKS + W1_BLKS + W2_BLKS, 256>>>(x, w1, w2);
    moe_gemm_mma<DD, FF, true ><<<dim3(FF / 128, CC / 128, EE), 256, GEMM_SMEM>>>(b1, nullptr);
    moe_gemm_mma<FF, DD, false><<<dim3(DD / 128, CC / 128, EE), 256, GEMM_SMEM>>>(b2, out);
}